// round 2
// baseline (speedup 1.0000x reference)
#include <cuda_runtime.h>

#define VN   64
#define BN   200
#define NSW  10
#define ECNT 63
#define MN   73
#define FIN  32
#define HID  64
#define MAXE 146
#define NT   512
#define OUTW (MN + VN + MN)   // 210

// ---------------- persistent topology (derived from inputs each launch) ----
__device__ int   g_ne;
__device__ int   g_ev[MAXE], g_ew[MAXE], g_efl[MAXE];
__device__ int   g_off[VN + 1];
__device__ int   g_slot[NSW];
__device__ float g_dinv[VN];

__global__ void preproc_kernel(const float* __restrict__ A,
                               const float* __restrict__ S,
                               const int*   __restrict__ edgeS) {
    __shared__ int cnt[VN];
    __shared__ int off[VN + 1];
    int v = threadIdx.x;
    if (v < VN) {
        int c = 0;
        for (int w = 0; w < VN; w++)
            if (A[v * VN + w] + S[v * VN + w] > 0.5f) c++;
        cnt[v] = c;
        g_dinv[v] = 1.0f / fmaxf((float)c, 1.0f);
    }
    __syncthreads();
    if (v == 0) {
        int s = 0;
        for (int i = 0; i < VN; i++) { off[i] = s; s += cnt[i]; }
        off[VN] = s;
        g_ne = (s > MAXE) ? MAXE : s;
    }
    __syncthreads();
    if (v < VN) {
        g_off[v] = off[v];
        if (v == 0) g_off[VN] = off[VN];
        int e = off[v];
        for (int w = 0; w < VN; w++) {
            if (A[v * VN + w] + S[v * VN + w] > 0.5f) {
                if (e < MAXE) {
                    g_ev[e]  = v;
                    g_ew[e]  = w;
                    g_efl[e] = (S[v * VN + w] > 0.5f) ? 1 : 0;
                }
                e++;
            }
        }
    }
    __syncthreads();
    if (v < NSW) {
        int si = edgeS[v], sj = edgeS[NSW + v];
        int slot = 0;
        for (int e = off[si]; e < off[si + 1]; e++)
            if (g_ew[e] == sj) slot = e;
        g_slot[v] = slot;
    }
}

// ---------------- shared memory layout (floats) ----------------------------
// sS   [MAXE*HID]   edge state (146x64)      -> reused as smlp hidden (10x256)
// sX   [VN*HID]     node state
// sB0  [VN*HID]     XI / XV                  \
// sB1  [VN*HID]     XJ / XU+msg               }-> contiguous: cmlp hidden (63x192)
// sW   [VN*HID]     Ws stage                 /
// small buffers + int topology copies
constexpr int O_S    = 0;
constexpr int O_X    = O_S  + MAXE * HID;       // 9344
constexpr int O_B0   = O_X  + VN * HID;         // 13440
constexpr int O_B1   = O_B0 + VN * HID;         // 17536
constexpr int O_W    = O_B1 + VN * HID;         // 21632
constexpr int O_XG   = O_W  + VN * HID;         // 25728
constexpr int O_EMB  = O_XG + HID;              // 25792
constexpr int O_SW   = O_EMB + 2 * FIN;         // 25856
constexpr int O_G    = O_SW + NSW * HID;        // 26496
constexpr int O_OUTS = O_G + 192;               // 26688
constexpr int O_OUTC = O_OUTS + 40;             // 26728
constexpr int O_VP   = O_OUTC + 192;            // 26920
constexpr int O_VC   = O_VP + 80;               // 27000
constexpr int O_DI   = O_VC + 80;               // 27080
constexpr int O_FEND = O_DI + VN;               // 27144 floats

constexpr int I_EV   = 0;
constexpr int I_EW   = I_EV + MAXE;
constexpr int I_EFL  = I_EW + MAXE;
constexpr int I_OFF  = I_EFL + MAXE;            // 65 ints
constexpr int I_AI   = I_OFF + VN + 1 + 2;      // pad
constexpr int I_AJ   = I_AI + 64;
constexpr int I_SI   = I_AJ + 64;
constexpr int I_SJ   = I_SI + 16;
constexpr int I_SLOT = I_SJ + 16;
constexpr int I_END  = I_SLOT + 16;

constexpr int SMEM_BYTES = O_FEND * 4 + I_END * 4;

__device__ __forceinline__ float sigm(float z) {
    return 1.0f / (1.0f + __expf(-z));
}

__global__ __launch_bounds__(NT)
void gnn_kernel(const float* __restrict__ x_in,
                const float* __restrict__ embed_s,
                const float* __restrict__ p0_Ws, const float* __restrict__ p0_Wi,
                const float* __restrict__ p0_Wj, const float* __restrict__ p0_U,
                const float* __restrict__ p0_V,
                const float* __restrict__ pl_Ws, const float* __restrict__ pl_Wi,
                const float* __restrict__ pl_Wj, const float* __restrict__ pl_U,
                const float* __restrict__ pl_V,
                const float* __restrict__ sW1,  const float* __restrict__ sW2,
                const float* __restrict__ cW1,  const float* __restrict__ cW2,
                const float* __restrict__ Dinv, const float* __restrict__ Incp,
                const float* __restrict__ Incc,
                const int*   __restrict__ edgeA, const int* __restrict__ edgeS,
                float* __restrict__ out) {
    extern __shared__ float smf[];
    float* sS   = smf + O_S;
    float* sX   = smf + O_X;
    float* sB0  = smf + O_B0;
    float* sB1  = smf + O_B1;
    float* sW   = smf + O_W;
    float* sXg  = smf + O_XG;
    float* sEmb = smf + O_EMB;
    float* sSw  = smf + O_SW;
    float* sG   = smf + O_G;
    float* sOutS= smf + O_OUTS;
    float* sOutC= smf + O_OUTC;
    float* sVp  = smf + O_VP;
    float* sVc  = smf + O_VC;
    float* sDi  = smf + O_DI;
    int*   smi  = (int*)(smf + O_FEND);
    int* sEv = smi + I_EV;  int* sEw = smi + I_EW;  int* sEfl = smi + I_EFL;
    int* sOff= smi + I_OFF; int* sAi = smi + I_AI;  int* sAj  = smi + I_AJ;
    int* sSi = smi + I_SI;  int* sSj = smi + I_SJ;  int* sSlot= smi + I_SLOT;
    float* sHid = smf + O_B0;   // 63*192 = 12096 <= 12288 contiguous (B0,B1,W)

    const int t    = threadIdx.x;
    const int b    = blockIdx.x;
    const int lane = t & 31;
    const int wid  = t >> 5;
    const int ne   = g_ne;

    // ---- load per-batch x and topology into shared -------------------------
    for (int i = t; i < VN * FIN; i += NT) {
        int v = i / FIN, h = i - v * FIN;
        sX[v * HID + h] = x_in[b * VN * FIN + i];
    }
    for (int i = t; i < ne; i += NT) {
        sEv[i] = g_ev[i]; sEw[i] = g_ew[i]; sEfl[i] = g_efl[i];
    }
    if (t <= VN) sOff[t] = g_off[t];
    if (t < VN)  { sDi[t] = g_dinv[t]; sEmb[t] = embed_s[t]; }
    if (t < ECNT){ sAi[t] = edgeA[t]; sAj[t] = edgeA[ECNT + t]; }
    if (t < NSW) { sSi[t] = edgeS[t]; sSj[t] = edgeS[NSW + t]; sSlot[t] = g_slot[t]; }
    __syncthreads();

    // ---- 3 GNN layers -------------------------------------------------------
    for (int l = 0; l < 3; l++) {
        const bool first = (l == 0);
        const int  F     = first ? FIN : HID;
        const float *Ws, *Wi, *Wj, *U, *Vw;
        if (first) { Ws = p0_Ws; Wi = p0_Wi; Wj = p0_Wj; U = p0_U; Vw = p0_V; }
        else {
            int o = (l - 1) * HID * HID;
            Ws = pl_Ws + o; Wi = pl_Wi + o; Wj = pl_Wj + o; U = pl_U + o; Vw = pl_V + o;
        }

        // XI -> sB0, XJ -> sB1 ; stage Ws into sW
        {
            int k = t & 63, vg = t >> 6;
            float aI[8], aJ[8];
            #pragma unroll
            for (int j = 0; j < 8; j++) { aI[j] = 0.f; aJ[j] = 0.f; }
            for (int h = 0; h < F; h++) {
                float wi = Wi[h * HID + k], wj = Wj[h * HID + k];
                #pragma unroll
                for (int j = 0; j < 8; j++) {
                    float xv = sX[(vg * 8 + j) * HID + h];
                    aI[j] = fmaf(xv, wi, aI[j]);
                    aJ[j] = fmaf(xv, wj, aJ[j]);
                }
            }
            #pragma unroll
            for (int j = 0; j < 8; j++) {
                sB0[(vg * 8 + j) * HID + k] = aI[j];
                sB1[(vg * 8 + j) * HID + k] = aJ[j];
            }
        }
        for (int i = t; i < F * HID; i += NT) sW[i] = Ws[i];
        __syncthreads();

        // edge update: e = relu(LN(s@Ws + XI[v] + XJ[w])) ; s = e or s+e
        for (int e = wid; e < ne; e += NT / 32) {
            int v = sEv[e], w = sEw[e];
            float a0 = 0.f, a1 = 0.f;
            if (first) {
                const float* em = sEmb + sEfl[e] * FIN;
                #pragma unroll 8
                for (int h = 0; h < FIN; h++) {
                    float sv = em[h];
                    a0 = fmaf(sv, sW[h * HID + lane],      a0);
                    a1 = fmaf(sv, sW[h * HID + lane + 32], a1);
                }
            } else {
                #pragma unroll 8
                for (int h = 0; h < HID; h++) {
                    float sv = sS[e * HID + h];
                    a0 = fmaf(sv, sW[h * HID + lane],      a0);
                    a1 = fmaf(sv, sW[h * HID + lane + 32], a1);
                }
            }
            float e0 = a0 + sB0[v * HID + lane]      + sB1[w * HID + lane];
            float e1 = a1 + sB0[v * HID + lane + 32] + sB1[w * HID + lane + 32];
            float s1 = e0 + e1, s2 = e0 * e0 + e1 * e1;
            #pragma unroll
            for (int o = 16; o > 0; o >>= 1) {
                s1 += __shfl_xor_sync(0xffffffffu, s1, o);
                s2 += __shfl_xor_sync(0xffffffffu, s2, o);
            }
            float mean = s1 * (1.0f / 64.0f);
            float var  = s2 * (1.0f / 64.0f) - mean * mean;
            float rs   = rsqrtf(var + 1e-5f);
            float r0 = fmaxf((e0 - mean) * rs, 0.0f);
            float r1 = fmaxf((e1 - mean) * rs, 0.0f);
            if (!first) { r0 += sS[e * HID + lane]; r1 += sS[e * HID + lane + 32]; }
            sS[e * HID + lane]      = r0;
            sS[e * HID + lane + 32] = r1;
        }
        __syncthreads();

        // XV -> sB0, XU -> sB1 (both from old x)
        {
            int k = t & 63, vg = t >> 6;
            float aV[8], aU[8];
            #pragma unroll
            for (int j = 0; j < 8; j++) { aV[j] = 0.f; aU[j] = 0.f; }
            for (int h = 0; h < F; h++) {
                float wv = Vw[h * HID + k], wu = U[h * HID + k];
                #pragma unroll
                for (int j = 0; j < 8; j++) {
                    float xv = sX[(vg * 8 + j) * HID + h];
                    aV[j] = fmaf(xv, wv, aV[j]);
                    aU[j] = fmaf(xv, wu, aU[j]);
                }
            }
            #pragma unroll
            for (int j = 0; j < 8; j++) {
                sB0[(vg * 8 + j) * HID + k] = aV[j];
                sB1[(vg * 8 + j) * HID + k] = aU[j];
            }
        }
        __syncthreads();

        // msg: sB1[v,k] += deg_inv[v] * sum_e sigmoid(s[e,k]) * XV[w_e,k]
        {
            int k = t & 63, vg = t >> 6;
            #pragma unroll
            for (int j = 0; j < 8; j++) {
                int v = vg * 8 + j;
                float acc = 0.f;
                int eb = sOff[v], ee = sOff[v + 1];
                for (int e = eb; e < ee; e++) {
                    float g = sigm(sS[e * HID + k]);
                    acc = fmaf(g, sB0[sEw[e] * HID + k], acc);
                }
                sB1[v * HID + k] += acc * sDi[v];
            }
        }
        __syncthreads();

        // node update: x = (x +) relu(LN(XU + msg))
        for (int v = wid; v < VN; v += NT / 32) {
            float z0 = sB1[v * HID + lane], z1 = sB1[v * HID + lane + 32];
            float s1 = z0 + z1, s2 = z0 * z0 + z1 * z1;
            #pragma unroll
            for (int o = 16; o > 0; o >>= 1) {
                s1 += __shfl_xor_sync(0xffffffffu, s1, o);
                s2 += __shfl_xor_sync(0xffffffffu, s2, o);
            }
            float mean = s1 * (1.0f / 64.0f);
            float var  = s2 * (1.0f / 64.0f) - mean * mean;
            float rs   = rsqrtf(var + 1e-5f);
            float r0 = fmaxf((z0 - mean) * rs, 0.0f);
            float r1 = fmaxf((z1 - mean) * rs, 0.0f);
            if (!first) { r0 += sX[v * HID + lane]; r1 += sX[v * HID + lane + 32]; }
            sX[v * HID + lane]      = r0;
            sX[v * HID + lane + 32] = r1;
        }
        __syncthreads();
    }

    // ---- heads --------------------------------------------------------------
    // snapshot switch-edge s rows, compute x_g
    for (int i = t; i < NSW * HID; i += NT) {
        int r = i >> 6, k = i & 63;
        sSw[i] = sS[sSlot[r] * HID + k];
    }
    if (t < HID) {
        float a = 0.f;
        for (int v = 0; v < VN; v++) a += sX[v * HID + t];
        sXg[t] = a;
    }
    __syncthreads();

    // smlp hidden (10 x 256) -> reuse sS
    {
        int k = t & 255, rg = t >> 8;       // rg in {0,1}, 5 rows each
        float acc[5];
        #pragma unroll
        for (int q = 0; q < 5; q++) acc[q] = 0.f;
        for (int i = 0; i < 64; i++) {
            float w = sW1[i * 256 + k];
            #pragma unroll
            for (int q = 0; q < 5; q++)
                acc[q] = fmaf(sSw[(rg * 5 + q) * HID + i], w, acc[q]);
        }
        for (int i = 0; i < 64; i++) {
            float w = sW1[(64 + i) * 256 + k];
            #pragma unroll
            for (int q = 0; q < 5; q++)
                acc[q] = fmaf(sX[sSi[rg * 5 + q] * HID + i], w, acc[q]);
        }
        for (int i = 0; i < 64; i++) {
            float w = sW1[(128 + i) * 256 + k];
            #pragma unroll
            for (int q = 0; q < 5; q++)
                acc[q] = fmaf(sX[sSj[rg * 5 + q] * HID + i], w, acc[q]);
        }
        for (int i = 0; i < 64; i++) {
            float w = sW1[(192 + i) * 256 + k];
            float g = sXg[i];
            #pragma unroll
            for (int q = 0; q < 5; q++) acc[q] = fmaf(g, w, acc[q]);
        }
        #pragma unroll
        for (int q = 0; q < 5; q++)
            sS[(rg * 5 + q) * 256 + k] = fmaxf(acc[q], 0.0f);
    }
    __syncthreads();

    // smlp out (10x4) + cmlp graph-term g[k] (192)
    if (t < NSW * 4) {
        int r = t >> 2, j = t & 3;
        float a = 0.f;
        for (int kk = 0; kk < 256; kk++)
            a = fmaf(sS[r * 256 + kk], sW2[kk * 4 + j], a);
        sOutS[t] = sigm(a);
    }
    if (t >= 64 && t < 256) {
        int k = t - 64;
        float a = 0.f;
        for (int i = 0; i < 64; i++)
            a = fmaf(sXg[i], cW1[(128 + i) * 192 + k], a);
        sG[k] = a;
    }
    __syncthreads();

    // cmlp hidden (63 x 192) -> sHid (reuses B0/B1/W arena)
    if (t < 384) {
        int k = t % 192, rg = t / 192;      // 2 row-groups of 32 (last row 62)
        float acc[32];
        int baseA[32], baseB[32];
        #pragma unroll
        for (int q = 0; q < 32; q++) {
            acc[q] = 0.f;
            int r = rg * 32 + q;
            int rr = (r < ECNT) ? r : 0;
            baseA[q] = sAi[rr] * HID;
            baseB[q] = sAj[rr] * HID;
        }
        for (int i = 0; i < 64; i++) {
            float w0 = cW1[i * 192 + k];
            float w1 = cW1[(64 + i) * 192 + k];
            #pragma unroll
            for (int q = 0; q < 32; q++) {
                acc[q] = fmaf(sX[baseA[q] + i], w0, acc[q]);
                acc[q] = fmaf(sX[baseB[q] + i], w1, acc[q]);
            }
        }
        #pragma unroll
        for (int q = 0; q < 32; q++) {
            int r = rg * 32 + q;
            if (r < ECNT)
                sHid[r * 192 + k] = fmaxf(acc[q] + sG[k], 0.0f);
        }
    }
    __syncthreads();

    // cmlp out (63x3)
    if (t < ECNT * 3) {
        int r = t / 3, j = t - r * 3;
        float a = 0.f;
        for (int kk = 0; kk < 192; kk++)
            a = fmaf(sHid[r * 192 + kk], cW2[kk * 3 + j], a);
        sOutC[t] = sigm(a);
    }
    __syncthreads();

    // per-edge parent/child voltages
    if (t < MN) {
        float o1, o2;
        if (t < ECNT) { o1 = sOutC[t * 3 + 1]; o2 = sOutC[t * 3 + 2]; }
        else          { o1 = sOutS[(t - ECNT) * 4 + 2]; o2 = sOutS[(t - ECNT) * 4 + 3]; }
        sVp[t] = 0.9f + 0.2f * o1;
        sVc[t] = 0.9f + 0.2f * o2;
    }
    __syncthreads();

    // ---- output assembly: [p_flow(73) | v(64) | graph_topo(73)] -------------
    float* ob = out + b * OUTW;
    for (int i = t; i < OUTW; i += NT) {
        float val;
        if (i < ECNT) {
            val = sOutC[i * 3] - 0.5f;
        } else if (i < MN) {
            val = sOutS[(i - ECNT) * 4 + 1] - 0.5f;
        } else if (i < MN + VN) {
            int n = i - MN;
            if (n == 0) val = 1.0f;
            else {
                float a = 0.f;
                for (int m = 0; m < MN; m++)
                    a += Incp[n * MN + m] * sVp[m] + Incc[n * MN + m] * sVc[m];
                val = Dinv[n * VN + n] * a;
            }
        } else if (i < MN + VN + ECNT) {
            val = 1.0f;
        } else {
            val = sOutS[(i - (MN + VN + ECNT)) * 4];
        }
        ob[i] = val;
    }
}

extern "C" void kernel_launch(void* const* d_in, const int* in_sizes, int n_in,
                              void* d_out, int out_size) {
    const float* x       = (const float*)d_in[0];
    const float* A       = (const float*)d_in[1];
    const float* S       = (const float*)d_in[2];
    const float* embed_s = (const float*)d_in[3];
    const float* p0_Ws   = (const float*)d_in[4];
    const float* p0_Wi   = (const float*)d_in[5];
    const float* p0_Wj   = (const float*)d_in[6];
    const float* p0_U    = (const float*)d_in[7];
    const float* p0_V    = (const float*)d_in[8];
    const float* pl_Ws   = (const float*)d_in[9];
    const float* pl_Wi   = (const float*)d_in[10];
    const float* pl_Wj   = (const float*)d_in[11];
    const float* pl_U    = (const float*)d_in[12];
    const float* pl_V    = (const float*)d_in[13];
    const float* smlp_W1 = (const float*)d_in[14];
    const float* smlp_W2 = (const float*)d_in[15];
    const float* cmlp_W1 = (const float*)d_in[16];
    const float* cmlp_W2 = (const float*)d_in[17];
    const float* Dinv    = (const float*)d_in[18];
    const float* Incp    = (const float*)d_in[19];
    const float* Incc    = (const float*)d_in[20];
    const int*   edge_A  = (const int*)d_in[21];
    const int*   edge_S  = (const int*)d_in[22];
    float*       out     = (float*)d_out;

    cudaFuncSetAttribute(gnn_kernel, cudaFuncAttributeMaxDynamicSharedMemorySize,
                         SMEM_BYTES);

    preproc_kernel<<<1, 64>>>(A, S, edge_S);
    gnn_kernel<<<BN, NT, SMEM_BYTES>>>(x, embed_s,
                                       p0_Ws, p0_Wi, p0_Wj, p0_U, p0_V,
                                       pl_Ws, pl_Wi, pl_Wj, pl_U, pl_V,
                                       smlp_W1, smlp_W2, cmlp_W1, cmlp_W2,
                                       Dinv, Incp, Incc, edge_A, edge_S, out);
}

// round 3
// speedup vs baseline: 1.0015x; 1.0015x over previous
#include <cuda_runtime.h>

#define VN   64
#define BN   200
#define NSW  10
#define ECNT 63
#define MN   73
#define FIN  32
#define HID  64
#define MAXE 146
#define NT   512
#define OUTW (MN + VN + MN)   // 210

// ---------------- persistent topology (derived from inputs each launch) ----
__device__ int   g_ne;
__device__ int   g_ev[MAXE], g_ew[MAXE], g_efl[MAXE];
__device__ int   g_off[VN + 1];
__device__ int   g_slot[NSW];
__device__ float g_dinv[VN];

__global__ void preproc_kernel(const float* __restrict__ A,
                               const float* __restrict__ S,
                               const int*   __restrict__ edgeS) {
    __shared__ int cnt[VN];
    __shared__ int off[VN + 1];
    int v = threadIdx.x;
    if (v < VN) {
        int c = 0;
        for (int w = 0; w < VN; w++)
            if (A[v * VN + w] + S[v * VN + w] > 0.5f) c++;
        cnt[v] = c;
        g_dinv[v] = 1.0f / fmaxf((float)c, 1.0f);
    }
    __syncthreads();
    if (v == 0) {
        int s = 0;
        for (int i = 0; i < VN; i++) { off[i] = s; s += cnt[i]; }
        off[VN] = s;
        g_ne = (s > MAXE) ? MAXE : s;
    }
    __syncthreads();
    if (v < VN) {
        g_off[v] = off[v];
        if (v == 0) g_off[VN] = off[VN];
        int e = off[v];
        for (int w = 0; w < VN; w++) {
            if (A[v * VN + w] + S[v * VN + w] > 0.5f) {
                if (e < MAXE) {
                    g_ev[e]  = v;
                    g_ew[e]  = w;
                    g_efl[e] = (S[v * VN + w] > 0.5f) ? 1 : 0;
                }
                e++;
            }
        }
    }
    __syncthreads();
    if (v < NSW) {
        int si = edgeS[v], sj = edgeS[NSW + v];
        int slot = 0;
        for (int e = off[si]; e < off[si + 1]; e++)
            if (g_ew[e] == sj) slot = e;
        g_slot[v] = slot;
    }
}

// ---------------- shared memory layout (floats) ----------------------------
// sS   [MAXE*HID]   edge state (146x64)      -> reused as smlp hidden (10x256)
// sX   [VN*HID]     node state
// sB0  [VN*HID]     XI / XV                  \
// sB1  [VN*HID]     XJ / XU+msg               }-> contiguous: cmlp hidden (63x192)
// sW   [VN*HID]     Ws stage                 /
// small buffers + int topology copies
constexpr int O_S    = 0;
constexpr int O_X    = O_S  + MAXE * HID;       // 9344
constexpr int O_B0   = O_X  + VN * HID;         // 13440
constexpr int O_B1   = O_B0 + VN * HID;         // 17536
constexpr int O_W    = O_B1 + VN * HID;         // 21632
constexpr int O_XG   = O_W  + VN * HID;         // 25728
constexpr int O_EMB  = O_XG + HID;              // 25792
constexpr int O_SW   = O_EMB + 2 * FIN;         // 25856
constexpr int O_G    = O_SW + NSW * HID;        // 26496
constexpr int O_OUTS = O_G + 192;               // 26688
constexpr int O_OUTC = O_OUTS + 40;             // 26728
constexpr int O_VP   = O_OUTC + 192;            // 26920
constexpr int O_VC   = O_VP + 80;               // 27000
constexpr int O_DI   = O_VC + 80;               // 27080
constexpr int O_FEND = O_DI + VN;               // 27144 floats

constexpr int I_EV   = 0;
constexpr int I_EW   = I_EV + MAXE;
constexpr int I_EFL  = I_EW + MAXE;
constexpr int I_OFF  = I_EFL + MAXE;            // 65 ints
constexpr int I_AI   = I_OFF + VN + 1 + 2;      // pad
constexpr int I_AJ   = I_AI + 64;
constexpr int I_SI   = I_AJ + 64;
constexpr int I_SJ   = I_SI + 16;
constexpr int I_SLOT = I_SJ + 16;
constexpr int I_END  = I_SLOT + 16;

constexpr int SMEM_BYTES = O_FEND * 4 + I_END * 4;

__device__ __forceinline__ float sigm(float z) {
    return 1.0f / (1.0f + __expf(-z));
}

__global__ __launch_bounds__(NT)
void gnn_kernel(const float* __restrict__ x_in,
                const float* __restrict__ embed_s,
                const float* __restrict__ p0_Ws, const float* __restrict__ p0_Wi,
                const float* __restrict__ p0_Wj, const float* __restrict__ p0_U,
                const float* __restrict__ p0_V,
                const float* __restrict__ pl_Ws, const float* __restrict__ pl_Wi,
                const float* __restrict__ pl_Wj, const float* __restrict__ pl_U,
                const float* __restrict__ pl_V,
                const float* __restrict__ sW1,  const float* __restrict__ sW2,
                const float* __restrict__ cW1,  const float* __restrict__ cW2,
                const float* __restrict__ Dinv, const float* __restrict__ Incp,
                const float* __restrict__ Incc,
                const int*   __restrict__ edgeA, const int* __restrict__ edgeS,
                float* __restrict__ out) {
    extern __shared__ float smf[];
    float* sS   = smf + O_S;
    float* sX   = smf + O_X;
    float* sB0  = smf + O_B0;
    float* sB1  = smf + O_B1;
    float* sW   = smf + O_W;
    float* sXg  = smf + O_XG;
    float* sEmb = smf + O_EMB;
    float* sSw  = smf + O_SW;
    float* sG   = smf + O_G;
    float* sOutS= smf + O_OUTS;
    float* sOutC= smf + O_OUTC;
    float* sVp  = smf + O_VP;
    float* sVc  = smf + O_VC;
    float* sDi  = smf + O_DI;
    int*   smi  = (int*)(smf + O_FEND);
    int* sEv = smi + I_EV;  int* sEw = smi + I_EW;  int* sEfl = smi + I_EFL;
    int* sOff= smi + I_OFF; int* sAi = smi + I_AI;  int* sAj  = smi + I_AJ;
    int* sSi = smi + I_SI;  int* sSj = smi + I_SJ;  int* sSlot= smi + I_SLOT;
    float* sHid = smf + O_B0;   // 63*192 = 12096 <= 12288 contiguous (B0,B1,W)

    const int t    = threadIdx.x;
    const int b    = blockIdx.x;
    const int lane = t & 31;
    const int wid  = t >> 5;
    const int ne   = g_ne;

    // ---- load per-batch x and topology into shared -------------------------
    for (int i = t; i < VN * FIN; i += NT) {
        int v = i / FIN, h = i - v * FIN;
        sX[v * HID + h] = x_in[b * VN * FIN + i];
    }
    for (int i = t; i < ne; i += NT) {
        sEv[i] = g_ev[i]; sEw[i] = g_ew[i]; sEfl[i] = g_efl[i];
    }
    if (t <= VN) sOff[t] = g_off[t];
    if (t < VN)  { sDi[t] = g_dinv[t]; sEmb[t] = embed_s[t]; }
    if (t < ECNT){ sAi[t] = edgeA[t]; sAj[t] = edgeA[ECNT + t]; }
    if (t < NSW) { sSi[t] = edgeS[t]; sSj[t] = edgeS[NSW + t]; sSlot[t] = g_slot[t]; }
    __syncthreads();

    // ---- 3 GNN layers -------------------------------------------------------
    for (int l = 0; l < 3; l++) {
        const bool first = (l == 0);
        const int  F     = first ? FIN : HID;
        const float *Ws, *Wi, *Wj, *U, *Vw;
        if (first) { Ws = p0_Ws; Wi = p0_Wi; Wj = p0_Wj; U = p0_U; Vw = p0_V; }
        else {
            int o = (l - 1) * HID * HID;
            Ws = pl_Ws + o; Wi = pl_Wi + o; Wj = pl_Wj + o; U = pl_U + o; Vw = pl_V + o;
        }

        // XI -> sB0, XJ -> sB1 ; stage Ws into sW
        {
            int k = t & 63, vg = t >> 6;
            float aI[8], aJ[8];
            #pragma unroll
            for (int j = 0; j < 8; j++) { aI[j] = 0.f; aJ[j] = 0.f; }
            for (int h = 0; h < F; h++) {
                float wi = Wi[h * HID + k], wj = Wj[h * HID + k];
                #pragma unroll
                for (int j = 0; j < 8; j++) {
                    float xv = sX[(vg * 8 + j) * HID + h];
                    aI[j] = fmaf(xv, wi, aI[j]);
                    aJ[j] = fmaf(xv, wj, aJ[j]);
                }
            }
            #pragma unroll
            for (int j = 0; j < 8; j++) {
                sB0[(vg * 8 + j) * HID + k] = aI[j];
                sB1[(vg * 8 + j) * HID + k] = aJ[j];
            }
        }
        for (int i = t; i < F * HID; i += NT) sW[i] = Ws[i];
        __syncthreads();

        // edge update: e = relu(LN(s@Ws + XI[v] + XJ[w])) ; s = e or s+e
        for (int e = wid; e < ne; e += NT / 32) {
            int v = sEv[e], w = sEw[e];
            float a0 = 0.f, a1 = 0.f;
            if (first) {
                const float* em = sEmb + sEfl[e] * FIN;
                #pragma unroll 8
                for (int h = 0; h < FIN; h++) {
                    float sv = em[h];
                    a0 = fmaf(sv, sW[h * HID + lane],      a0);
                    a1 = fmaf(sv, sW[h * HID + lane + 32], a1);
                }
            } else {
                #pragma unroll 8
                for (int h = 0; h < HID; h++) {
                    float sv = sS[e * HID + h];
                    a0 = fmaf(sv, sW[h * HID + lane],      a0);
                    a1 = fmaf(sv, sW[h * HID + lane + 32], a1);
                }
            }
            float e0 = a0 + sB0[v * HID + lane]      + sB1[w * HID + lane];
            float e1 = a1 + sB0[v * HID + lane + 32] + sB1[w * HID + lane + 32];
            float s1 = e0 + e1, s2 = e0 * e0 + e1 * e1;
            #pragma unroll
            for (int o = 16; o > 0; o >>= 1) {
                s1 += __shfl_xor_sync(0xffffffffu, s1, o);
                s2 += __shfl_xor_sync(0xffffffffu, s2, o);
            }
            float mean = s1 * (1.0f / 64.0f);
            float var  = s2 * (1.0f / 64.0f) - mean * mean;
            float rs   = rsqrtf(var + 1e-5f);
            float r0 = fmaxf((e0 - mean) * rs, 0.0f);
            float r1 = fmaxf((e1 - mean) * rs, 0.0f);
            if (!first) { r0 += sS[e * HID + lane]; r1 += sS[e * HID + lane + 32]; }
            sS[e * HID + lane]      = r0;
            sS[e * HID + lane + 32] = r1;
        }
        __syncthreads();

        // XV -> sB0, XU -> sB1 (both from old x)
        {
            int k = t & 63, vg = t >> 6;
            float aV[8], aU[8];
            #pragma unroll
            for (int j = 0; j < 8; j++) { aV[j] = 0.f; aU[j] = 0.f; }
            for (int h = 0; h < F; h++) {
                float wv = Vw[h * HID + k], wu = U[h * HID + k];
                #pragma unroll
                for (int j = 0; j < 8; j++) {
                    float xv = sX[(vg * 8 + j) * HID + h];
                    aV[j] = fmaf(xv, wv, aV[j]);
                    aU[j] = fmaf(xv, wu, aU[j]);
                }
            }
            #pragma unroll
            for (int j = 0; j < 8; j++) {
                sB0[(vg * 8 + j) * HID + k] = aV[j];
                sB1[(vg * 8 + j) * HID + k] = aU[j];
            }
        }
        __syncthreads();

        // msg: sB1[v,k] += deg_inv[v] * sum_e sigmoid(s[e,k]) * XV[w_e,k]
        {
            int k = t & 63, vg = t >> 6;
            #pragma unroll
            for (int j = 0; j < 8; j++) {
                int v = vg * 8 + j;
                float acc = 0.f;
                int eb = sOff[v], ee = sOff[v + 1];
                for (int e = eb; e < ee; e++) {
                    float g = sigm(sS[e * HID + k]);
                    acc = fmaf(g, sB0[sEw[e] * HID + k], acc);
                }
                sB1[v * HID + k] += acc * sDi[v];
            }
        }
        __syncthreads();

        // node update: x = (x +) relu(LN(XU + msg))
        for (int v = wid; v < VN; v += NT / 32) {
            float z0 = sB1[v * HID + lane], z1 = sB1[v * HID + lane + 32];
            float s1 = z0 + z1, s2 = z0 * z0 + z1 * z1;
            #pragma unroll
            for (int o = 16; o > 0; o >>= 1) {
                s1 += __shfl_xor_sync(0xffffffffu, s1, o);
                s2 += __shfl_xor_sync(0xffffffffu, s2, o);
            }
            float mean = s1 * (1.0f / 64.0f);
            float var  = s2 * (1.0f / 64.0f) - mean * mean;
            float rs   = rsqrtf(var + 1e-5f);
            float r0 = fmaxf((z0 - mean) * rs, 0.0f);
            float r1 = fmaxf((z1 - mean) * rs, 0.0f);
            if (!first) { r0 += sX[v * HID + lane]; r1 += sX[v * HID + lane + 32]; }
            sX[v * HID + lane]      = r0;
            sX[v * HID + lane + 32] = r1;
        }
        __syncthreads();
    }

    // ---- heads --------------------------------------------------------------
    // snapshot switch-edge s rows, compute x_g
    for (int i = t; i < NSW * HID; i += NT) {
        int r = i >> 6, k = i & 63;
        sSw[i] = sS[sSlot[r] * HID + k];
    }
    if (t < HID) {
        float a = 0.f;
        for (int v = 0; v < VN; v++) a += sX[v * HID + t];
        sXg[t] = a;
    }
    __syncthreads();

    // smlp hidden (10 x 256) -> reuse sS
    {
        int k = t & 255, rg = t >> 8;       // rg in {0,1}, 5 rows each
        float acc[5];
        #pragma unroll
        for (int q = 0; q < 5; q++) acc[q] = 0.f;
        for (int i = 0; i < 64; i++) {
            float w = sW1[i * 256 + k];
            #pragma unroll
            for (int q = 0; q < 5; q++)
                acc[q] = fmaf(sSw[(rg * 5 + q) * HID + i], w, acc[q]);
        }
        for (int i = 0; i < 64; i++) {
            float w = sW1[(64 + i) * 256 + k];
            #pragma unroll
            for (int q = 0; q < 5; q++)
                acc[q] = fmaf(sX[sSi[rg * 5 + q] * HID + i], w, acc[q]);
        }
        for (int i = 0; i < 64; i++) {
            float w = sW1[(128 + i) * 256 + k];
            #pragma unroll
            for (int q = 0; q < 5; q++)
                acc[q] = fmaf(sX[sSj[rg * 5 + q] * HID + i], w, acc[q]);
        }
        for (int i = 0; i < 64; i++) {
            float w = sW1[(192 + i) * 256 + k];
            float g = sXg[i];
            #pragma unroll
            for (int q = 0; q < 5; q++) acc[q] = fmaf(g, w, acc[q]);
        }
        #pragma unroll
        for (int q = 0; q < 5; q++)
            sS[(rg * 5 + q) * 256 + k] = fmaxf(acc[q], 0.0f);
    }
    __syncthreads();

    // smlp out (10x4) + cmlp graph-term g[k] (192)
    if (t < NSW * 4) {
        int r = t >> 2, j = t & 3;
        float a = 0.f;
        for (int kk = 0; kk < 256; kk++)
            a = fmaf(sS[r * 256 + kk], sW2[kk * 4 + j], a);
        sOutS[t] = sigm(a);
    }
    if (t >= 64 && t < 256) {
        int k = t - 64;
        float a = 0.f;
        for (int i = 0; i < 64; i++)
            a = fmaf(sXg[i], cW1[(128 + i) * 192 + k], a);
        sG[k] = a;
    }
    __syncthreads();

    // cmlp hidden (63 x 192) -> sHid (reuses B0/B1/W arena)
    if (t < 384) {
        int k = t % 192, rg = t / 192;      // 2 row-groups of 32 (last row 62)
        float acc[32];
        int baseA[32], baseB[32];
        #pragma unroll
        for (int q = 0; q < 32; q++) {
            acc[q] = 0.f;
            int r = rg * 32 + q;
            int rr = (r < ECNT) ? r : 0;
            baseA[q] = sAi[rr] * HID;
            baseB[q] = sAj[rr] * HID;
        }
        for (int i = 0; i < 64; i++) {
            float w0 = cW1[i * 192 + k];
            float w1 = cW1[(64 + i) * 192 + k];
            #pragma unroll
            for (int q = 0; q < 32; q++) {
                acc[q] = fmaf(sX[baseA[q] + i], w0, acc[q]);
                acc[q] = fmaf(sX[baseB[q] + i], w1, acc[q]);
            }
        }
        #pragma unroll
        for (int q = 0; q < 32; q++) {
            int r = rg * 32 + q;
            if (r < ECNT)
                sHid[r * 192 + k] = fmaxf(acc[q] + sG[k], 0.0f);
        }
    }
    __syncthreads();

    // cmlp out (63x3)
    if (t < ECNT * 3) {
        int r = t / 3, j = t - r * 3;
        float a = 0.f;
        for (int kk = 0; kk < 192; kk++)
            a = fmaf(sHid[r * 192 + kk], cW2[kk * 3 + j], a);
        sOutC[t] = sigm(a);
    }
    __syncthreads();

    // per-edge parent/child voltages
    if (t < MN) {
        float o1, o2;
        if (t < ECNT) { o1 = sOutC[t * 3 + 1]; o2 = sOutC[t * 3 + 2]; }
        else          { o1 = sOutS[(t - ECNT) * 4 + 2]; o2 = sOutS[(t - ECNT) * 4 + 3]; }
        sVp[t] = 0.9f + 0.2f * o1;
        sVc[t] = 0.9f + 0.2f * o2;
    }
    __syncthreads();

    // ---- output assembly: [p_flow(73) | v(64) | graph_topo(73)] -------------
    float* ob = out + b * OUTW;
    for (int i = t; i < OUTW; i += NT) {
        float val;
        if (i < ECNT) {
            val = sOutC[i * 3] - 0.5f;
        } else if (i < MN) {
            val = sOutS[(i - ECNT) * 4 + 1] - 0.5f;
        } else if (i < MN + VN) {
            int n = i - MN;
            if (n == 0) val = 1.0f;
            else {
                float a = 0.f;
                for (int m = 0; m < MN; m++)
                    a += Incp[n * MN + m] * sVp[m] + Incc[n * MN + m] * sVc[m];
                val = Dinv[n * VN + n] * a;
            }
        } else if (i < MN + VN + ECNT) {
            val = 1.0f;
        } else {
            val = sOutS[(i - (MN + VN + ECNT)) * 4];
        }
        ob[i] = val;
    }
}

extern "C" void kernel_launch(void* const* d_in, const int* in_sizes, int n_in,
                              void* d_out, int out_size) {
    const float* x       = (const float*)d_in[0];
    const float* A       = (const float*)d_in[1];
    const float* S       = (const float*)d_in[2];
    const float* embed_s = (const float*)d_in[3];
    const float* p0_Ws   = (const float*)d_in[4];
    const float* p0_Wi   = (const float*)d_in[5];
    const float* p0_Wj   = (const float*)d_in[6];
    const float* p0_U    = (const float*)d_in[7];
    const float* p0_V    = (const float*)d_in[8];
    const float* pl_Ws   = (const float*)d_in[9];
    const float* pl_Wi   = (const float*)d_in[10];
    const float* pl_Wj   = (const float*)d_in[11];
    const float* pl_U    = (const float*)d_in[12];
    const float* pl_V    = (const float*)d_in[13];
    const float* smlp_W1 = (const float*)d_in[14];
    const float* smlp_W2 = (const float*)d_in[15];
    const float* cmlp_W1 = (const float*)d_in[16];
    const float* cmlp_W2 = (const float*)d_in[17];
    const float* Dinv    = (const float*)d_in[18];
    const float* Incp    = (const float*)d_in[19];
    const float* Incc    = (const float*)d_in[20];
    const int*   edge_A  = (const int*)d_in[21];
    const int*   edge_S  = (const int*)d_in[22];
    float*       out     = (float*)d_out;

    cudaFuncSetAttribute(gnn_kernel, cudaFuncAttributeMaxDynamicSharedMemorySize,
                         SMEM_BYTES);

    preproc_kernel<<<1, 64>>>(A, S, edge_S);
    gnn_kernel<<<BN, NT, SMEM_BYTES>>>(x, embed_s,
                                       p0_Ws, p0_Wi, p0_Wj, p0_U, p0_V,
                                       pl_Ws, pl_Wi, pl_Wj, pl_U, pl_V,
                                       smlp_W1, smlp_W2, cmlp_W1, cmlp_W2,
                                       Dinv, Incp, Incc, edge_A, edge_S, out);
}

// round 4
// speedup vs baseline: 1.1725x; 1.1707x over previous
#include <cuda_runtime.h>

#define VN   64
#define BN   200
#define NSW  10
#define ECNT 63
#define MN   73
#define FIN  32
#define HID  64
#define MAXE 146
#define NT   512
#define OUTW (MN + VN + MN)   // 210

// ---------------- persistent topology (derived from inputs each launch) ----
__device__ int   g_ne;
__device__ int   g_ev[MAXE], g_ew[MAXE], g_efl[MAXE];
__device__ int   g_off[VN + 1];
__device__ int   g_slot[NSW];
__device__ float g_dinv[VN];

__global__ void preproc_kernel(const float* __restrict__ A,
                               const float* __restrict__ S,
                               const int*   __restrict__ edgeS) {
    __shared__ int cnt[VN];
    __shared__ int off[VN + 1];
    int v = threadIdx.x;
    if (v < VN) {
        int c = 0;
        for (int w = 0; w < VN; w++)
            if (A[v * VN + w] + S[v * VN + w] > 0.5f) c++;
        cnt[v] = c;
        g_dinv[v] = 1.0f / fmaxf((float)c, 1.0f);
    }
    __syncthreads();
    if (v == 0) {
        int s = 0;
        for (int i = 0; i < VN; i++) { off[i] = s; s += cnt[i]; }
        off[VN] = s;
        g_ne = (s > MAXE) ? MAXE : s;
    }
    __syncthreads();
    if (v < VN) {
        g_off[v] = off[v];
        if (v == 0) g_off[VN] = off[VN];
        int e = off[v];
        for (int w = 0; w < VN; w++) {
            if (A[v * VN + w] + S[v * VN + w] > 0.5f) {
                if (e < MAXE) {
                    g_ev[e]  = v;
                    g_ew[e]  = w;
                    g_efl[e] = (S[v * VN + w] > 0.5f) ? 1 : 0;
                }
                e++;
            }
        }
    }
    __syncthreads();
    if (v < NSW) {
        int si = edgeS[v], sj = edgeS[NSW + v];
        int slot = 0;
        for (int e = off[si]; e < off[si + 1]; e++)
            if (g_ew[e] == sj) slot = e;
        g_slot[v] = slot;
    }
}

// ---------------- shared memory layout (floats) ----------------------------
constexpr int O_S    = 0;
constexpr int O_X    = O_S  + MAXE * HID;       // 9344
constexpr int O_B0   = O_X  + VN * HID;         // 13440
constexpr int O_B1   = O_B0 + VN * HID;         // 17536
constexpr int O_W    = O_B1 + VN * HID;         // 21632
constexpr int O_XG   = O_W  + VN * HID;         // 25728
constexpr int O_EMB  = O_XG + HID;              // 25792
constexpr int O_SW   = O_EMB + 2 * FIN;         // 25856
constexpr int O_G    = O_SW + NSW * HID;        // 26496
constexpr int O_OUTS = O_G + 192;               // 26688
constexpr int O_OUTC = O_OUTS + 40;             // 26728
constexpr int O_VP   = O_OUTC + 192;            // 26920
constexpr int O_VC   = O_VP + 80;               // 27000
constexpr int O_DI   = O_VC + 80;               // 27080
constexpr int O_FEND = O_DI + VN;               // 27144 floats

constexpr int I_EV   = 0;
constexpr int I_EW   = I_EV + MAXE;
constexpr int I_EFL  = I_EW + MAXE;
constexpr int I_OFF  = I_EFL + MAXE;
constexpr int I_AI   = I_OFF + VN + 1 + 2;
constexpr int I_AJ   = I_AI + 64;
constexpr int I_SI   = I_AJ + 64;
constexpr int I_SJ   = I_SI + 16;
constexpr int I_SLOT = I_SJ + 16;
constexpr int I_END  = I_SLOT + 16;

constexpr int SMEM_BYTES = O_FEND * 4 + I_END * 4;   // ~111.3 KB -> 2 CTAs/SM

__device__ __forceinline__ float sigm(float z) {
    return 1.0f / (1.0f + __expf(-z));
}

__global__ __launch_bounds__(NT, 2)
void gnn_kernel(const float* __restrict__ x_in,
                const float* __restrict__ embed_s,
                const float* __restrict__ p0_Ws, const float* __restrict__ p0_Wi,
                const float* __restrict__ p0_Wj, const float* __restrict__ p0_U,
                const float* __restrict__ p0_V,
                const float* __restrict__ pl_Ws, const float* __restrict__ pl_Wi,
                const float* __restrict__ pl_Wj, const float* __restrict__ pl_U,
                const float* __restrict__ pl_V,
                const float* __restrict__ sW1,  const float* __restrict__ sW2,
                const float* __restrict__ cW1,  const float* __restrict__ cW2,
                const float* __restrict__ Dinv, const float* __restrict__ Incp,
                const float* __restrict__ Incc,
                const int*   __restrict__ edgeA, const int* __restrict__ edgeS,
                float* __restrict__ out) {
    extern __shared__ float smf[];
    float* sS   = smf + O_S;
    float* sX   = smf + O_X;
    float* sB0  = smf + O_B0;
    float* sB1  = smf + O_B1;
    float* sW   = smf + O_W;
    float* sXg  = smf + O_XG;
    float* sEmb = smf + O_EMB;
    float* sSw  = smf + O_SW;
    float* sG   = smf + O_G;
    float* sOutS= smf + O_OUTS;
    float* sOutC= smf + O_OUTC;
    float* sVp  = smf + O_VP;
    float* sVc  = smf + O_VC;
    float* sDi  = smf + O_DI;
    int*   smi  = (int*)(smf + O_FEND);
    int* sEv = smi + I_EV;  int* sEw = smi + I_EW;  int* sEfl = smi + I_EFL;
    int* sOff= smi + I_OFF; int* sAi = smi + I_AI;  int* sAj  = smi + I_AJ;
    int* sSi = smi + I_SI;  int* sSj = smi + I_SJ;  int* sSlot= smi + I_SLOT;
    float* sHid = smf + O_B0;   // 63*192 = 12096 <= 12288 contiguous (B0,B1,W)

    const int t    = threadIdx.x;
    const int b    = blockIdx.x;
    const int lane = t & 31;
    const int wid  = t >> 5;
    const int ne   = g_ne;

    // ---- load per-batch x and topology into shared -------------------------
    for (int i = t; i < VN * FIN; i += NT) {
        int v = i / FIN, h = i - v * FIN;
        sX[v * HID + h] = x_in[b * VN * FIN + i];
    }
    for (int i = t; i < ne; i += NT) {
        sEv[i] = g_ev[i]; sEw[i] = g_ew[i]; sEfl[i] = g_efl[i];
    }
    if (t <= VN) sOff[t] = g_off[t];
    if (t < VN)  { sDi[t] = g_dinv[t]; sEmb[t] = embed_s[t]; }
    if (t < ECNT){ sAi[t] = edgeA[t]; sAj[t] = edgeA[ECNT + t]; }
    if (t < NSW) { sSi[t] = edgeS[t]; sSj[t] = edgeS[NSW + t]; sSlot[t] = g_slot[t]; }
    __syncthreads();

    // ---- 3 GNN layers -------------------------------------------------------
    for (int l = 0; l < 3; l++) {
        const bool first = (l == 0);
        const int  F     = first ? FIN : HID;
        const float *Ws, *Wi, *Wj, *U, *Vw;
        if (first) { Ws = p0_Ws; Wi = p0_Wi; Wj = p0_Wj; U = p0_U; Vw = p0_V; }
        else {
            int o = (l - 1) * HID * HID;
            Ws = pl_Ws + o; Wi = pl_Wi + o; Wj = pl_Wj + o; U = pl_U + o; Vw = pl_V + o;
        }

        // XI -> sB0, XJ -> sB1 ; stage Ws into sW  (float2 over h)
        {
            int k = t & 63, vg = t >> 6;
            float aI[8], aJ[8];
            #pragma unroll
            for (int j = 0; j < 8; j++) { aI[j] = 0.f; aJ[j] = 0.f; }
            for (int h = 0; h < F; h += 2) {
                float wi0 = Wi[h * HID + k],       wj0 = Wj[h * HID + k];
                float wi1 = Wi[(h + 1) * HID + k], wj1 = Wj[(h + 1) * HID + k];
                #pragma unroll
                for (int j = 0; j < 8; j++) {
                    float2 xv = *(const float2*)&sX[(vg * 8 + j) * HID + h];
                    aI[j] = fmaf(xv.x, wi0, aI[j]);
                    aI[j] = fmaf(xv.y, wi1, aI[j]);
                    aJ[j] = fmaf(xv.x, wj0, aJ[j]);
                    aJ[j] = fmaf(xv.y, wj1, aJ[j]);
                }
            }
            #pragma unroll
            for (int j = 0; j < 8; j++) {
                sB0[(vg * 8 + j) * HID + k] = aI[j];
                sB1[(vg * 8 + j) * HID + k] = aJ[j];
            }
        }
        for (int i = t; i < F * HID; i += NT) sW[i] = Ws[i];
        __syncthreads();

        // edge update: e = relu(LN(s@Ws + XI[v] + XJ[w])) ; s = e or s+e
        for (int e = wid; e < ne; e += NT / 32) {
            int v = sEv[e], w = sEw[e];
            float a0 = 0.f, a1 = 0.f;
            if (first) {
                const float* em = sEmb + sEfl[e] * FIN;
                #pragma unroll 8
                for (int h = 0; h < FIN; h += 2) {
                    float2 sv = *(const float2*)&em[h];
                    a0 = fmaf(sv.x, sW[h * HID + lane],            a0);
                    a1 = fmaf(sv.x, sW[h * HID + lane + 32],       a1);
                    a0 = fmaf(sv.y, sW[(h + 1) * HID + lane],      a0);
                    a1 = fmaf(sv.y, sW[(h + 1) * HID + lane + 32], a1);
                }
            } else {
                #pragma unroll 8
                for (int h = 0; h < HID; h += 2) {
                    float2 sv = *(const float2*)&sS[e * HID + h];
                    a0 = fmaf(sv.x, sW[h * HID + lane],            a0);
                    a1 = fmaf(sv.x, sW[h * HID + lane + 32],       a1);
                    a0 = fmaf(sv.y, sW[(h + 1) * HID + lane],      a0);
                    a1 = fmaf(sv.y, sW[(h + 1) * HID + lane + 32], a1);
                }
            }
            float e0 = a0 + sB0[v * HID + lane]      + sB1[w * HID + lane];
            float e1 = a1 + sB0[v * HID + lane + 32] + sB1[w * HID + lane + 32];
            float s1 = e0 + e1, s2 = e0 * e0 + e1 * e1;
            #pragma unroll
            for (int o = 16; o > 0; o >>= 1) {
                s1 += __shfl_xor_sync(0xffffffffu, s1, o);
                s2 += __shfl_xor_sync(0xffffffffu, s2, o);
            }
            float mean = s1 * (1.0f / 64.0f);
            float var  = s2 * (1.0f / 64.0f) - mean * mean;
            float rs   = rsqrtf(var + 1e-5f);
            float r0 = fmaxf((e0 - mean) * rs, 0.0f);
            float r1 = fmaxf((e1 - mean) * rs, 0.0f);
            if (!first) { r0 += sS[e * HID + lane]; r1 += sS[e * HID + lane + 32]; }
            sS[e * HID + lane]      = r0;
            sS[e * HID + lane + 32] = r1;
        }
        __syncthreads();

        // XV -> sB0, XU -> sB1 (both from old x)  (float2 over h)
        {
            int k = t & 63, vg = t >> 6;
            float aV[8], aU[8];
            #pragma unroll
            for (int j = 0; j < 8; j++) { aV[j] = 0.f; aU[j] = 0.f; }
            for (int h = 0; h < F; h += 2) {
                float wv0 = Vw[h * HID + k],       wu0 = U[h * HID + k];
                float wv1 = Vw[(h + 1) * HID + k], wu1 = U[(h + 1) * HID + k];
                #pragma unroll
                for (int j = 0; j < 8; j++) {
                    float2 xv = *(const float2*)&sX[(vg * 8 + j) * HID + h];
                    aV[j] = fmaf(xv.x, wv0, aV[j]);
                    aV[j] = fmaf(xv.y, wv1, aV[j]);
                    aU[j] = fmaf(xv.x, wu0, aU[j]);
                    aU[j] = fmaf(xv.y, wu1, aU[j]);
                }
            }
            #pragma unroll
            for (int j = 0; j < 8; j++) {
                sB0[(vg * 8 + j) * HID + k] = aV[j];
                sB1[(vg * 8 + j) * HID + k] = aU[j];
            }
        }
        __syncthreads();

        // msg: sB1[v,k] += deg_inv[v] * sum_e sigmoid(s[e,k]) * XV[w_e,k]
        {
            int k = t & 63, vg = t >> 6;
            #pragma unroll
            for (int j = 0; j < 8; j++) {
                int v = vg * 8 + j;
                float acc = 0.f;
                int eb = sOff[v], ee = sOff[v + 1];
                for (int e = eb; e < ee; e++) {
                    float g = sigm(sS[e * HID + k]);
                    acc = fmaf(g, sB0[sEw[e] * HID + k], acc);
                }
                sB1[v * HID + k] += acc * sDi[v];
            }
        }
        __syncthreads();

        // node update: x = (x +) relu(LN(XU + msg))
        for (int v = wid; v < VN; v += NT / 32) {
            float z0 = sB1[v * HID + lane], z1 = sB1[v * HID + lane + 32];
            float s1 = z0 + z1, s2 = z0 * z0 + z1 * z1;
            #pragma unroll
            for (int o = 16; o > 0; o >>= 1) {
                s1 += __shfl_xor_sync(0xffffffffu, s1, o);
                s2 += __shfl_xor_sync(0xffffffffu, s2, o);
            }
            float mean = s1 * (1.0f / 64.0f);
            float var  = s2 * (1.0f / 64.0f) - mean * mean;
            float rs   = rsqrtf(var + 1e-5f);
            float r0 = fmaxf((z0 - mean) * rs, 0.0f);
            float r1 = fmaxf((z1 - mean) * rs, 0.0f);
            if (!first) { r0 += sX[v * HID + lane]; r1 += sX[v * HID + lane + 32]; }
            sX[v * HID + lane]      = r0;
            sX[v * HID + lane + 32] = r1;
        }
        __syncthreads();
    }

    // ---- heads --------------------------------------------------------------
    for (int i = t; i < NSW * HID; i += NT) {
        int r = i >> 6, k = i & 63;
        sSw[i] = sS[sSlot[r] * HID + k];
    }
    if (t < HID) {
        float a = 0.f;
        for (int v = 0; v < VN; v++) a += sX[v * HID + t];
        sXg[t] = a;
    }
    __syncthreads();

    // smlp hidden (10 x 256) -> reuse sS
    {
        int k = t & 255, rg = t >> 8;       // rg in {0,1}, 5 rows each
        float acc[5];
        #pragma unroll
        for (int q = 0; q < 5; q++) acc[q] = 0.f;
        for (int i = 0; i < 64; i++) {
            float w = sW1[i * 256 + k];
            #pragma unroll
            for (int q = 0; q < 5; q++)
                acc[q] = fmaf(sSw[(rg * 5 + q) * HID + i], w, acc[q]);
        }
        for (int i = 0; i < 64; i++) {
            float w = sW1[(64 + i) * 256 + k];
            #pragma unroll
            for (int q = 0; q < 5; q++)
                acc[q] = fmaf(sX[sSi[rg * 5 + q] * HID + i], w, acc[q]);
        }
        for (int i = 0; i < 64; i++) {
            float w = sW1[(128 + i) * 256 + k];
            #pragma unroll
            for (int q = 0; q < 5; q++)
                acc[q] = fmaf(sX[sSj[rg * 5 + q] * HID + i], w, acc[q]);
        }
        for (int i = 0; i < 64; i++) {
            float w = sW1[(192 + i) * 256 + k];
            float g = sXg[i];
            #pragma unroll
            for (int q = 0; q < 5; q++) acc[q] = fmaf(g, w, acc[q]);
        }
        #pragma unroll
        for (int q = 0; q < 5; q++)
            sS[(rg * 5 + q) * 256 + k] = fmaxf(acc[q], 0.0f);
    }
    __syncthreads();

    // smlp out (10x4) + cmlp graph-term g[k] (192)
    if (t < NSW * 4) {
        int r = t >> 2, j = t & 3;
        float a = 0.f;
        for (int kk = 0; kk < 256; kk++)
            a = fmaf(sS[r * 256 + kk], sW2[kk * 4 + j], a);
        sOutS[t] = sigm(a);
    }
    if (t >= 64 && t < 256) {
        int k = t - 64;
        float a = 0.f;
        for (int i = 0; i < 64; i++)
            a = fmaf(sXg[i], cW1[(128 + i) * 192 + k], a);
        sG[k] = a;
    }
    __syncthreads();

    // cmlp hidden (63 x 192) -> sHid, 4 passes of 8 rows -> low reg pressure
    if (t < 384) {
        int k = t % 192, half = t / 192;
        #pragma unroll 1
        for (int p = 0; p < 4; p++) {
            int r0 = p * 16 + half * 8;
            float acc[8];
            int bA[8], bB[8];
            #pragma unroll
            for (int q = 0; q < 8; q++) {
                int r = r0 + q;
                int rr = (r < ECNT) ? r : 0;
                acc[q] = 0.f;
                bA[q] = sAi[rr] * HID;
                bB[q] = sAj[rr] * HID;
            }
            for (int i = 0; i < 64; i++) {
                float w0 = cW1[i * 192 + k];
                float w1 = cW1[(64 + i) * 192 + k];
                #pragma unroll
                for (int q = 0; q < 8; q++) {
                    acc[q] = fmaf(sX[bA[q] + i], w0, acc[q]);
                    acc[q] = fmaf(sX[bB[q] + i], w1, acc[q]);
                }
            }
            #pragma unroll
            for (int q = 0; q < 8; q++) {
                int r = r0 + q;
                if (r < ECNT)
                    sHid[r * 192 + k] = fmaxf(acc[q] + sG[k], 0.0f);
            }
        }
    }
    __syncthreads();

    // cmlp out (63x3)
    if (t < ECNT * 3) {
        int r = t / 3, j = t - r * 3;
        float a = 0.f;
        for (int kk = 0; kk < 192; kk++)
            a = fmaf(sHid[r * 192 + kk], cW2[kk * 3 + j], a);
        sOutC[t] = sigm(a);
    }
    __syncthreads();

    // per-edge parent/child voltages
    if (t < MN) {
        float o1, o2;
        if (t < ECNT) { o1 = sOutC[t * 3 + 1]; o2 = sOutC[t * 3 + 2]; }
        else          { o1 = sOutS[(t - ECNT) * 4 + 2]; o2 = sOutS[(t - ECNT) * 4 + 3]; }
        sVp[t] = 0.9f + 0.2f * o1;
        sVc[t] = 0.9f + 0.2f * o2;
    }
    __syncthreads();

    // ---- output assembly: [p_flow(73) | v(64) | graph_topo(73)] -------------
    float* ob = out + b * OUTW;
    for (int i = t; i < OUTW; i += NT) {
        float val;
        if (i < ECNT) {
            val = sOutC[i * 3] - 0.5f;
        } else if (i < MN) {
            val = sOutS[(i - ECNT) * 4 + 1] - 0.5f;
        } else if (i < MN + VN) {
            int n = i - MN;
            if (n == 0) val = 1.0f;
            else {
                float a = 0.f;
                for (int m = 0; m < MN; m++)
                    a += Incp[n * MN + m] * sVp[m] + Incc[n * MN + m] * sVc[m];
                val = Dinv[n * VN + n] * a;
            }
        } else if (i < MN + VN + ECNT) {
            val = 1.0f;
        } else {
            val = sOutS[(i - (MN + VN + ECNT)) * 4];
        }
        ob[i] = val;
    }
}

extern "C" void kernel_launch(void* const* d_in, const int* in_sizes, int n_in,
                              void* d_out, int out_size) {
    const float* x       = (const float*)d_in[0];
    const float* A       = (const float*)d_in[1];
    const float* S       = (const float*)d_in[2];
    const float* embed_s = (const float*)d_in[3];
    const float* p0_Ws   = (const float*)d_in[4];
    const float* p0_Wi   = (const float*)d_in[5];
    const float* p0_Wj   = (const float*)d_in[6];
    const float* p0_U    = (const float*)d_in[7];
    const float* p0_V    = (const float*)d_in[8];
    const float* pl_Ws   = (const float*)d_in[9];
    const float* pl_Wi   = (const float*)d_in[10];
    const float* pl_Wj   = (const float*)d_in[11];
    const float* pl_U    = (const float*)d_in[12];
    const float* pl_V    = (const float*)d_in[13];
    const float* smlp_W1 = (const float*)d_in[14];
    const float* smlp_W2 = (const float*)d_in[15];
    const float* cmlp_W1 = (const float*)d_in[16];
    const float* cmlp_W2 = (const float*)d_in[17];
    const float* Dinv    = (const float*)d_in[18];
    const float* Incp    = (const float*)d_in[19];
    const float* Incc    = (const float*)d_in[20];
    const int*   edge_A  = (const int*)d_in[21];
    const int*   edge_S  = (const int*)d_in[22];
    float*       out     = (float*)d_out;

    cudaFuncSetAttribute(gnn_kernel, cudaFuncAttributeMaxDynamicSharedMemorySize,
                         SMEM_BYTES);

    preproc_kernel<<<1, 64>>>(A, S, edge_S);
    gnn_kernel<<<BN, NT, SMEM_BYTES>>>(x, embed_s,
                                       p0_Ws, p0_Wi, p0_Wj, p0_U, p0_V,
                                       pl_Ws, pl_Wi, pl_Wj, pl_U, pl_V,
                                       smlp_W1, smlp_W2, cmlp_W1, cmlp_W2,
                                       Dinv, Incp, Incc, edge_A, edge_S, out);
}

// round 5
// speedup vs baseline: 1.3925x; 1.1876x over previous
#include <cuda_runtime.h>

#define VN   64
#define BN   200
#define NSW  10
#define ECNT 63
#define MN   73
#define FIN  32
#define HID  64
#define MAXE 146
#define NT   512
#define NWARP (NT / 32)
#define NE_W 10           // ceil(MAXE / NWARP)
#define OUTW (MN + VN + MN)   // 210

// ---------------- persistent topology (derived from inputs each launch) ----
__device__ int   g_ne;
__device__ int   g_ev[MAXE], g_ew[MAXE], g_efl[MAXE];
__device__ int   g_off[VN + 1];
__device__ int   g_slot[NSW];
__device__ float g_dinv[VN];

__global__ void preproc_kernel(const float* __restrict__ A,
                               const float* __restrict__ S,
                               const int*   __restrict__ edgeS) {
    __shared__ int cnt[VN];
    __shared__ int off[VN + 1];
    int v = threadIdx.x;
    if (v < VN) {
        int c = 0;
        for (int w = 0; w < VN; w++)
            if (A[v * VN + w] + S[v * VN + w] > 0.5f) c++;
        cnt[v] = c;
        g_dinv[v] = 1.0f / fmaxf((float)c, 1.0f);
    }
    __syncthreads();
    if (v == 0) {
        int s = 0;
        for (int i = 0; i < VN; i++) { off[i] = s; s += cnt[i]; }
        off[VN] = s;
        g_ne = (s > MAXE) ? MAXE : s;
    }
    __syncthreads();
    if (v < VN) {
        g_off[v] = off[v];
        if (v == 0) g_off[VN] = off[VN];
        int e = off[v];
        for (int w = 0; w < VN; w++) {
            if (A[v * VN + w] + S[v * VN + w] > 0.5f) {
                if (e < MAXE) {
                    g_ev[e]  = v;
                    g_ew[e]  = w;
                    g_efl[e] = (S[v * VN + w] > 0.5f) ? 1 : 0;
                }
                e++;
            }
        }
    }
    __syncthreads();
    if (v < NSW) {
        int si = edgeS[v], sj = edgeS[NSW + v];
        int slot = 0;
        for (int e = off[si]; e < off[si + 1]; e++)
            if (g_ew[e] == sj) slot = e;
        g_slot[v] = slot;
    }
}

// ---------------- shared memory layout (floats) ----------------------------
constexpr int O_S    = 0;
constexpr int O_X    = O_S  + MAXE * HID;       // 9344
constexpr int O_B0   = O_X  + VN * HID;         // 13440
constexpr int O_B1   = O_B0 + VN * HID;         // 17536
constexpr int O_W    = O_B1 + VN * HID;         // 21632
constexpr int O_XG   = O_W  + VN * HID;         // 25728
constexpr int O_EMB  = O_XG + HID;              // 25792
constexpr int O_SW   = O_EMB + 2 * FIN;         // 25856
constexpr int O_G    = O_SW + NSW * HID;        // 26496
constexpr int O_OUTS = O_G + 192;               // 26688
constexpr int O_OUTC = O_OUTS + 40;             // 26728
constexpr int O_VP   = O_OUTC + 192;            // 26920
constexpr int O_VC   = O_VP + 80;               // 27000
constexpr int O_DI   = O_VC + 80;               // 27080
constexpr int O_FEND = O_DI + VN;               // 27144 floats

constexpr int I_EV   = 0;
constexpr int I_EW   = I_EV + MAXE;
constexpr int I_EFL  = I_EW + MAXE;
constexpr int I_OFF  = I_EFL + MAXE;
constexpr int I_AI   = I_OFF + VN + 1 + 2;
constexpr int I_AJ   = I_AI + 64;
constexpr int I_SI   = I_AJ + 64;
constexpr int I_SJ   = I_SI + 16;
constexpr int I_SLOT = I_SJ + 16;
constexpr int I_END  = I_SLOT + 16;

constexpr int SMEM_BYTES = O_FEND * 4 + I_END * 4;   // ~111.3 KB -> 2 CTAs/SM

__device__ __forceinline__ float sigm(float z) {
    return 1.0f / (1.0f + __expf(-z));
}

__global__ __launch_bounds__(NT, 2)
void gnn_kernel(const float* __restrict__ x_in,
                const float* __restrict__ embed_s,
                const float* __restrict__ p0_Ws, const float* __restrict__ p0_Wi,
                const float* __restrict__ p0_Wj, const float* __restrict__ p0_U,
                const float* __restrict__ p0_V,
                const float* __restrict__ pl_Ws, const float* __restrict__ pl_Wi,
                const float* __restrict__ pl_Wj, const float* __restrict__ pl_U,
                const float* __restrict__ pl_V,
                const float* __restrict__ sW1,  const float* __restrict__ sW2,
                const float* __restrict__ cW1,  const float* __restrict__ cW2,
                const float* __restrict__ Dinv, const float* __restrict__ Incp,
                const float* __restrict__ Incc,
                const int*   __restrict__ edgeA, const int* __restrict__ edgeS,
                float* __restrict__ out) {
    extern __shared__ float smf[];
    float* sS   = smf + O_S;
    float* sX   = smf + O_X;
    float* sB0  = smf + O_B0;
    float* sB1  = smf + O_B1;
    float* sW   = smf + O_W;
    float* sXg  = smf + O_XG;
    float* sEmb = smf + O_EMB;
    float* sSw  = smf + O_SW;
    float* sG   = smf + O_G;
    float* sOutS= smf + O_OUTS;
    float* sOutC= smf + O_OUTC;
    float* sVp  = smf + O_VP;
    float* sVc  = smf + O_VC;
    float* sDi  = smf + O_DI;
    int*   smi  = (int*)(smf + O_FEND);
    int* sEv = smi + I_EV;  int* sEw = smi + I_EW;  int* sEfl = smi + I_EFL;
    int* sOff= smi + I_OFF; int* sAi = smi + I_AI;  int* sAj  = smi + I_AJ;
    int* sSi = smi + I_SI;  int* sSj = smi + I_SJ;  int* sSlot= smi + I_SLOT;
    float* sHid = smf + O_B0;   // 63*192 = 12096 <= 12288 contiguous (B0,B1,W)

    const int t    = threadIdx.x;
    const int b    = blockIdx.x;
    const int lane = t & 31;
    const int wid  = t >> 5;
    const int ne   = g_ne;

    // ---- load per-batch x and topology into shared -------------------------
    for (int i = t; i < VN * FIN; i += NT) {
        int v = i / FIN, h = i - v * FIN;
        sX[v * HID + h] = x_in[b * VN * FIN + i];
    }
    for (int i = t; i < ne; i += NT) {
        sEv[i] = g_ev[i]; sEw[i] = g_ew[i]; sEfl[i] = g_efl[i];
    }
    if (t <= VN) sOff[t] = g_off[t];
    if (t < VN)  { sDi[t] = g_dinv[t]; sEmb[t] = embed_s[t]; }
    if (t < ECNT){ sAi[t] = edgeA[t]; sAj[t] = edgeA[ECNT + t]; }
    if (t < NSW) { sSi[t] = edgeS[t]; sSj[t] = edgeS[NSW + t]; sSlot[t] = g_slot[t]; }
    __syncthreads();

    // ---- 3 GNN layers -------------------------------------------------------
    for (int l = 0; l < 3; l++) {
        const bool first = (l == 0);
        const int  F     = first ? FIN : HID;
        const float *Ws, *Wi, *Wj, *U, *Vw;
        if (first) { Ws = p0_Ws; Wi = p0_Wi; Wj = p0_Wj; U = p0_U; Vw = p0_V; }
        else {
            int o = (l - 1) * HID * HID;
            Ws = pl_Ws + o; Wi = pl_Wi + o; Wj = pl_Wj + o; U = pl_U + o; Vw = pl_V + o;
        }

        // XI -> sB0, XJ -> sB1 ; stage Ws into sW  (float2 over h)
        {
            int k = t & 63, vg = t >> 6;
            float aI[8], aJ[8];
            #pragma unroll
            for (int j = 0; j < 8; j++) { aI[j] = 0.f; aJ[j] = 0.f; }
            for (int h = 0; h < F; h += 2) {
                float wi0 = Wi[h * HID + k],       wj0 = Wj[h * HID + k];
                float wi1 = Wi[(h + 1) * HID + k], wj1 = Wj[(h + 1) * HID + k];
                #pragma unroll
                for (int j = 0; j < 8; j++) {
                    float2 xv = *(const float2*)&sX[(vg * 8 + j) * HID + h];
                    aI[j] = fmaf(xv.x, wi0, aI[j]);
                    aI[j] = fmaf(xv.y, wi1, aI[j]);
                    aJ[j] = fmaf(xv.x, wj0, aJ[j]);
                    aJ[j] = fmaf(xv.y, wj1, aJ[j]);
                }
            }
            #pragma unroll
            for (int j = 0; j < 8; j++) {
                sB0[(vg * 8 + j) * HID + k] = aI[j];
                sB1[(vg * 8 + j) * HID + k] = aJ[j];
            }
        }
        for (int i = t; i < F * HID; i += NT) sW[i] = Ws[i];
        __syncthreads();

        // ---- edge update: e = relu(LN(s@Ws + XI[v] + XJ[w])) ; s = e or s+e
        // warp batches its NE_W edges; weights hoisted per h-chunk, sS rows
        // broadcast as float4.
        {
            float acc0[NE_W], acc1[NE_W];
            int   soff[NE_W];
            #pragma unroll
            for (int q = 0; q < NE_W; q++) {
                acc0[q] = 0.f; acc1[q] = 0.f;
                int e  = wid + q * NWARP;
                int ec = (e < ne) ? e : 0;
                soff[q] = first ? (sEfl[ec] * FIN) : (ec * HID);
            }
            const float* sbase = first ? sEmb : sS;
            for (int h = 0; h < F; h += 4) {
                float w00 = sW[(h    ) * HID + lane];
                float w01 = sW[(h + 1) * HID + lane];
                float w02 = sW[(h + 2) * HID + lane];
                float w03 = sW[(h + 3) * HID + lane];
                float w10 = sW[(h    ) * HID + lane + 32];
                float w11 = sW[(h + 1) * HID + lane + 32];
                float w12 = sW[(h + 2) * HID + lane + 32];
                float w13 = sW[(h + 3) * HID + lane + 32];
                #pragma unroll
                for (int q = 0; q < NE_W; q++) {
                    float4 sv = *(const float4*)&sbase[soff[q] + h];
                    acc0[q] = fmaf(sv.x, w00, acc0[q]);
                    acc0[q] = fmaf(sv.y, w01, acc0[q]);
                    acc0[q] = fmaf(sv.z, w02, acc0[q]);
                    acc0[q] = fmaf(sv.w, w03, acc0[q]);
                    acc1[q] = fmaf(sv.x, w10, acc1[q]);
                    acc1[q] = fmaf(sv.y, w11, acc1[q]);
                    acc1[q] = fmaf(sv.z, w12, acc1[q]);
                    acc1[q] = fmaf(sv.w, w13, acc1[q]);
                }
            }
            #pragma unroll
            for (int q = 0; q < NE_W; q++) {
                int e = wid + q * NWARP;        // warp-uniform
                if (e < ne) {
                    int v = sEv[e], w = sEw[e];
                    float e0 = acc0[q] + sB0[v * HID + lane]      + sB1[w * HID + lane];
                    float e1 = acc1[q] + sB0[v * HID + lane + 32] + sB1[w * HID + lane + 32];
                    float s1 = e0 + e1, s2 = e0 * e0 + e1 * e1;
                    #pragma unroll
                    for (int o = 16; o > 0; o >>= 1) {
                        s1 += __shfl_xor_sync(0xffffffffu, s1, o);
                        s2 += __shfl_xor_sync(0xffffffffu, s2, o);
                    }
                    float mean = s1 * (1.0f / 64.0f);
                    float var  = s2 * (1.0f / 64.0f) - mean * mean;
                    float rs   = rsqrtf(var + 1e-5f);
                    float r0 = fmaxf((e0 - mean) * rs, 0.0f);
                    float r1 = fmaxf((e1 - mean) * rs, 0.0f);
                    if (!first) { r0 += sS[e * HID + lane]; r1 += sS[e * HID + lane + 32]; }
                    sS[e * HID + lane]      = r0;
                    sS[e * HID + lane + 32] = r1;
                }
            }
        }
        __syncthreads();

        // XV -> sB0, XU -> sB1 (both from old x)  (float2 over h)
        {
            int k = t & 63, vg = t >> 6;
            float aV[8], aU[8];
            #pragma unroll
            for (int j = 0; j < 8; j++) { aV[j] = 0.f; aU[j] = 0.f; }
            for (int h = 0; h < F; h += 2) {
                float wv0 = Vw[h * HID + k],       wu0 = U[h * HID + k];
                float wv1 = Vw[(h + 1) * HID + k], wu1 = U[(h + 1) * HID + k];
                #pragma unroll
                for (int j = 0; j < 8; j++) {
                    float2 xv = *(const float2*)&sX[(vg * 8 + j) * HID + h];
                    aV[j] = fmaf(xv.x, wv0, aV[j]);
                    aV[j] = fmaf(xv.y, wv1, aV[j]);
                    aU[j] = fmaf(xv.x, wu0, aU[j]);
                    aU[j] = fmaf(xv.y, wu1, aU[j]);
                }
            }
            #pragma unroll
            for (int j = 0; j < 8; j++) {
                sB0[(vg * 8 + j) * HID + k] = aV[j];
                sB1[(vg * 8 + j) * HID + k] = aU[j];
            }
        }
        __syncthreads();

        // msg: sB1[v,k] += deg_inv[v] * sum_e sigmoid(s[e,k]) * XV[w_e,k]
        {
            int k = t & 63, vg = t >> 6;
            #pragma unroll
            for (int j = 0; j < 8; j++) {
                int v = vg * 8 + j;
                float acc = 0.f;
                int eb = sOff[v], ee = sOff[v + 1];
                for (int e = eb; e < ee; e++) {
                    float g = sigm(sS[e * HID + k]);
                    acc = fmaf(g, sB0[sEw[e] * HID + k], acc);
                }
                sB1[v * HID + k] += acc * sDi[v];
            }
        }
        __syncthreads();

        // node update: x = (x +) relu(LN(XU + msg))
        for (int v = wid; v < VN; v += NWARP) {
            float z0 = sB1[v * HID + lane], z1 = sB1[v * HID + lane + 32];
            float s1 = z0 + z1, s2 = z0 * z0 + z1 * z1;
            #pragma unroll
            for (int o = 16; o > 0; o >>= 1) {
                s1 += __shfl_xor_sync(0xffffffffu, s1, o);
                s2 += __shfl_xor_sync(0xffffffffu, s2, o);
            }
            float mean = s1 * (1.0f / 64.0f);
            float var  = s2 * (1.0f / 64.0f) - mean * mean;
            float rs   = rsqrtf(var + 1e-5f);
            float r0 = fmaxf((z0 - mean) * rs, 0.0f);
            float r1 = fmaxf((z1 - mean) * rs, 0.0f);
            if (!first) { r0 += sX[v * HID + lane]; r1 += sX[v * HID + lane + 32]; }
            sX[v * HID + lane]      = r0;
            sX[v * HID + lane + 32] = r1;
        }
        __syncthreads();
    }

    // ---- heads --------------------------------------------------------------
    for (int i = t; i < NSW * HID; i += NT) {
        int r = i >> 6, k = i & 63;
        sSw[i] = sS[sSlot[r] * HID + k];
    }
    if (t < HID) {
        float a = 0.f;
        for (int v = 0; v < VN; v++) a += sX[v * HID + t];
        sXg[t] = a;
    }
    __syncthreads();

    // smlp hidden (10 x 256) -> reuse sS
    {
        int k = t & 255, rg = t >> 8;       // rg in {0,1}, 5 rows each
        float acc[5];
        #pragma unroll
        for (int q = 0; q < 5; q++) acc[q] = 0.f;
        for (int i = 0; i < 64; i++) {
            float w = sW1[i * 256 + k];
            #pragma unroll
            for (int q = 0; q < 5; q++)
                acc[q] = fmaf(sSw[(rg * 5 + q) * HID + i], w, acc[q]);
        }
        for (int i = 0; i < 64; i++) {
            float w = sW1[(64 + i) * 256 + k];
            #pragma unroll
            for (int q = 0; q < 5; q++)
                acc[q] = fmaf(sX[sSi[rg * 5 + q] * HID + i], w, acc[q]);
        }
        for (int i = 0; i < 64; i++) {
            float w = sW1[(128 + i) * 256 + k];
            #pragma unroll
            for (int q = 0; q < 5; q++)
                acc[q] = fmaf(sX[sSj[rg * 5 + q] * HID + i], w, acc[q]);
        }
        for (int i = 0; i < 64; i++) {
            float w = sW1[(192 + i) * 256 + k];
            float g = sXg[i];
            #pragma unroll
            for (int q = 0; q < 5; q++) acc[q] = fmaf(g, w, acc[q]);
        }
        #pragma unroll
        for (int q = 0; q < 5; q++)
            sS[(rg * 5 + q) * 256 + k] = fmaxf(acc[q], 0.0f);
    }
    __syncthreads();

    // smlp out (10x4) + cmlp graph-term g[k] (192)
    if (t < NSW * 4) {
        int r = t >> 2, j = t & 3;
        float a = 0.f;
        for (int kk = 0; kk < 256; kk++)
            a = fmaf(sS[r * 256 + kk], sW2[kk * 4 + j], a);
        sOutS[t] = sigm(a);
    }
    if (t >= 64 && t < 256) {
        int k = t - 64;
        float a = 0.f;
        for (int i = 0; i < 64; i++)
            a = fmaf(sXg[i], cW1[(128 + i) * 192 + k], a);
        sG[k] = a;
    }
    __syncthreads();

    // cmlp hidden (63 x 192) -> sHid, 4 passes of 8 rows -> low reg pressure
    if (t < 384) {
        int k = t % 192, half = t / 192;
        #pragma unroll 1
        for (int p = 0; p < 4; p++) {
            int r0 = p * 16 + half * 8;
            float acc[8];
            int bA[8], bB[8];
            #pragma unroll
            for (int q = 0; q < 8; q++) {
                int r = r0 + q;
                int rr = (r < ECNT) ? r : 0;
                acc[q] = 0.f;
                bA[q] = sAi[rr] * HID;
                bB[q] = sAj[rr] * HID;
            }
            for (int i = 0; i < 64; i++) {
                float w0 = cW1[i * 192 + k];
                float w1 = cW1[(64 + i) * 192 + k];
                #pragma unroll
                for (int q = 0; q < 8; q++) {
                    acc[q] = fmaf(sX[bA[q] + i], w0, acc[q]);
                    acc[q] = fmaf(sX[bB[q] + i], w1, acc[q]);
                }
            }
            #pragma unroll
            for (int q = 0; q < 8; q++) {
                int r = r0 + q;
                if (r < ECNT)
                    sHid[r * 192 + k] = fmaxf(acc[q] + sG[k], 0.0f);
            }
        }
    }
    __syncthreads();

    // cmlp out (63x3)
    if (t < ECNT * 3) {
        int r = t / 3, j = t - r * 3;
        float a = 0.f;
        for (int kk = 0; kk < 192; kk++)
            a = fmaf(sHid[r * 192 + kk], cW2[kk * 3 + j], a);
        sOutC[t] = sigm(a);
    }
    __syncthreads();

    // per-edge parent/child voltages; zero node accumulator (reuse sXg)
    if (t < MN) {
        float o1, o2;
        if (t < ECNT) { o1 = sOutC[t * 3 + 1]; o2 = sOutC[t * 3 + 2]; }
        else          { o1 = sOutS[(t - ECNT) * 4 + 2]; o2 = sOutS[(t - ECNT) * 4 + 3]; }
        sVp[t] = 0.9f + 0.2f * o1;
        sVc[t] = 0.9f + 0.2f * o2;
    }
    if (t < VN) sXg[t] = 0.f;
    __syncthreads();

    // scatter voltages to nodes via shared atomics (Incp/Incc are one-hot)
    if (t < MN) {
        int p = (t < ECNT) ? sAi[t] : sSi[t - ECNT];
        int c = (t < ECNT) ? sAj[t] : sSj[t - ECNT];
        atomicAdd(&sXg[p], sVp[t]);
        atomicAdd(&sXg[c], sVc[t]);
    }
    __syncthreads();

    // ---- output assembly: [p_flow(73) | v(64) | graph_topo(73)] -------------
    float* ob = out + b * OUTW;
    for (int i = t; i < OUTW; i += NT) {
        float val;
        if (i < ECNT) {
            val = sOutC[i * 3] - 0.5f;
        } else if (i < MN) {
            val = sOutS[(i - ECNT) * 4 + 1] - 0.5f;
        } else if (i < MN + VN) {
            int n = i - MN;
            val = (n == 0) ? 1.0f : Dinv[n * VN + n] * sXg[n];
        } else if (i < MN + VN + ECNT) {
            val = 1.0f;
        } else {
            val = sOutS[(i - (MN + VN + ECNT)) * 4];
        }
        ob[i] = val;
    }
}

extern "C" void kernel_launch(void* const* d_in, const int* in_sizes, int n_in,
                              void* d_out, int out_size) {
    const float* x       = (const float*)d_in[0];
    const float* A       = (const float*)d_in[1];
    const float* S       = (const float*)d_in[2];
    const float* embed_s = (const float*)d_in[3];
    const float* p0_Ws   = (const float*)d_in[4];
    const float* p0_Wi   = (const float*)d_in[5];
    const float* p0_Wj   = (const float*)d_in[6];
    const float* p0_U    = (const float*)d_in[7];
    const float* p0_V    = (const float*)d_in[8];
    const float* pl_Ws   = (const float*)d_in[9];
    const float* pl_Wi   = (const float*)d_in[10];
    const float* pl_Wj   = (const float*)d_in[11];
    const float* pl_U    = (const float*)d_in[12];
    const float* pl_V    = (const float*)d_in[13];
    const float* smlp_W1 = (const float*)d_in[14];
    const float* smlp_W2 = (const float*)d_in[15];
    const float* cmlp_W1 = (const float*)d_in[16];
    const float* cmlp_W2 = (const float*)d_in[17];
    const float* Dinv    = (const float*)d_in[18];
    const float* Incp    = (const float*)d_in[19];
    const float* Incc    = (const float*)d_in[20];
    const int*   edge_A  = (const int*)d_in[21];
    const int*   edge_S  = (const int*)d_in[22];
    float*       out     = (float*)d_out;

    cudaFuncSetAttribute(gnn_kernel, cudaFuncAttributeMaxDynamicSharedMemorySize,
                         SMEM_BYTES);

    preproc_kernel<<<1, 64>>>(A, S, edge_S);
    gnn_kernel<<<BN, NT, SMEM_BYTES>>>(x, embed_s,
                                       p0_Ws, p0_Wi, p0_Wj, p0_U, p0_V,
                                       pl_Ws, pl_Wi, pl_Wj, pl_U, pl_V,
                                       smlp_W1, smlp_W2, cmlp_W1, cmlp_W2,
                                       Dinv, Incp, Incc, edge_A, edge_S, out);
}

// round 6
// speedup vs baseline: 1.4062x; 1.0098x over previous
#include <cuda_runtime.h>

#define VN   64
#define BN   200
#define NSW  10
#define ECNT 63
#define MN   73
#define FIN  32
#define HID  64
#define MAXE 146
#define NT   512
#define NWARP (NT / 32)
#define NE_W 10           // ceil(MAXE / NWARP)
#define WPAD 68           // padded transposed-weight row (float4-aligned, conflict-free)
#define OUTW (MN + VN + MN)   // 210

// ---------------- persistent topology (derived from inputs each launch) ----
__device__ int   g_ne;
__device__ int   g_ev[MAXE], g_ew[MAXE], g_efl[MAXE];
__device__ int   g_off[VN + 1];
__device__ int   g_slot[NSW];
__device__ float g_dinv[VN];

__global__ void preproc_kernel(const float* __restrict__ A,
                               const float* __restrict__ S,
                               const int*   __restrict__ edgeS) {
    __shared__ int cnt[VN];
    __shared__ int off[VN + 1];
    int v = threadIdx.x;
    if (v < VN) {
        int c = 0;
        for (int w = 0; w < VN; w++)
            if (A[v * VN + w] + S[v * VN + w] > 0.5f) c++;
        cnt[v] = c;
        g_dinv[v] = 1.0f / fmaxf((float)c, 1.0f);
    }
    __syncthreads();
    if (v == 0) {
        int s = 0;
        for (int i = 0; i < VN; i++) { off[i] = s; s += cnt[i]; }
        off[VN] = s;
        g_ne = (s > MAXE) ? MAXE : s;
    }
    __syncthreads();
    if (v < VN) {
        g_off[v] = off[v];
        if (v == 0) g_off[VN] = off[VN];
        int e = off[v];
        for (int w = 0; w < VN; w++) {
            if (A[v * VN + w] + S[v * VN + w] > 0.5f) {
                if (e < MAXE) {
                    g_ev[e]  = v;
                    g_ew[e]  = w;
                    g_efl[e] = (S[v * VN + w] > 0.5f) ? 1 : 0;
                }
                e++;
            }
        }
    }
    __syncthreads();
    if (v < NSW) {
        int si = edgeS[v], sj = edgeS[NSW + v];
        int slot = 0;
        for (int e = off[si]; e < off[si + 1]; e++)
            if (g_ew[e] == sj) slot = e;
        g_slot[v] = slot;
    }
}

// ---------------- shared memory layout (floats) ----------------------------
constexpr int O_S    = 0;
constexpr int O_X    = O_S  + MAXE * HID;       // 9344
constexpr int O_B0   = O_X  + VN * HID;         // 13440
constexpr int O_B1   = O_B0 + VN * HID;         // 17536
constexpr int O_W    = O_B1 + VN * HID;         // 21632  (transposed, 64*WPAD)
constexpr int O_XG   = O_W  + HID * WPAD;       // 25984
constexpr int O_EMB  = O_XG + HID;              // 26048
constexpr int O_SW   = O_EMB + 2 * FIN;         // 26112
constexpr int O_G    = O_SW + NSW * HID;        // 26752
constexpr int O_OUTS = O_G + 192;               // 26944
constexpr int O_OUTC = O_OUTS + 40;             // 26984
constexpr int O_VP   = O_OUTC + 192;            // 27176
constexpr int O_VC   = O_VP + 80;               // 27256
constexpr int O_DI   = O_VC + 80;               // 27336
constexpr int O_FEND = O_DI + VN;               // 27400 floats

constexpr int I_EV   = 0;
constexpr int I_EW   = I_EV + MAXE;
constexpr int I_EFL  = I_EW + MAXE;
constexpr int I_OFF  = I_EFL + MAXE;
constexpr int I_AI   = I_OFF + VN + 1 + 2;
constexpr int I_AJ   = I_AI + 64;
constexpr int I_SI   = I_AJ + 64;
constexpr int I_SJ   = I_SI + 16;
constexpr int I_SLOT = I_SJ + 16;
constexpr int I_END  = I_SLOT + 16;

constexpr int SMEM_BYTES = O_FEND * 4 + I_END * 4;   // ~112.3 KB -> 2 CTAs/SM

__device__ __forceinline__ float sigm(float z) {
    return 1.0f / (1.0f + __expf(-z));
}

__global__ __launch_bounds__(NT, 2)
void gnn_kernel(const float* __restrict__ x_in,
                const float* __restrict__ embed_s,
                const float* __restrict__ p0_Ws, const float* __restrict__ p0_Wi,
                const float* __restrict__ p0_Wj, const float* __restrict__ p0_U,
                const float* __restrict__ p0_V,
                const float* __restrict__ pl_Ws, const float* __restrict__ pl_Wi,
                const float* __restrict__ pl_Wj, const float* __restrict__ pl_U,
                const float* __restrict__ pl_V,
                const float* __restrict__ sW1,  const float* __restrict__ sW2,
                const float* __restrict__ cW1,  const float* __restrict__ cW2,
                const float* __restrict__ Dinv, const float* __restrict__ Incp,
                const float* __restrict__ Incc,
                const int*   __restrict__ edgeA, const int* __restrict__ edgeS,
                float* __restrict__ out) {
    extern __shared__ float smf[];
    float* sS   = smf + O_S;
    float* sX   = smf + O_X;
    float* sB0  = smf + O_B0;
    float* sB1  = smf + O_B1;
    float* sW   = smf + O_W;
    float* sXg  = smf + O_XG;
    float* sEmb = smf + O_EMB;
    float* sSw  = smf + O_SW;
    float* sG   = smf + O_G;
    float* sOutS= smf + O_OUTS;
    float* sOutC= smf + O_OUTC;
    float* sVp  = smf + O_VP;
    float* sVc  = smf + O_VC;
    float* sDi  = smf + O_DI;
    int*   smi  = (int*)(smf + O_FEND);
    int* sEv = smi + I_EV;  int* sEw = smi + I_EW;  int* sEfl = smi + I_EFL;
    int* sOff= smi + I_OFF; int* sAi = smi + I_AI;  int* sAj  = smi + I_AJ;
    int* sSi = smi + I_SI;  int* sSj = smi + I_SJ;  int* sSlot= smi + I_SLOT;
    float* sHid = smf + O_B0;   // 63*192 = 12096 <= 12544 contiguous (B0,B1,W)

    const int t    = threadIdx.x;
    const int b    = blockIdx.x;
    const int lane = t & 31;
    const int wid  = t >> 5;
    const int ne   = g_ne;

    // ---- load per-batch x (float4) and topology into shared -----------------
    {
        const float4* xi4 = (const float4*)(x_in + b * VN * FIN);
        int v = t >> 3, h = (t & 7) * 4;          // 512 float4 = whole tile
        *(float4*)&sX[v * HID + h] = xi4[t];
    }
    for (int i = t; i < ne; i += NT) {
        sEv[i] = g_ev[i]; sEw[i] = g_ew[i]; sEfl[i] = g_efl[i];
    }
    if (t <= VN) sOff[t] = g_off[t];
    if (t < VN)  { sDi[t] = g_dinv[t]; sEmb[t] = embed_s[t]; }
    if (t < ECNT){ sAi[t] = edgeA[t]; sAj[t] = edgeA[ECNT + t]; }
    if (t < NSW) { sSi[t] = edgeS[t]; sSj[t] = edgeS[NSW + t]; sSlot[t] = g_slot[t]; }
    __syncthreads();

    // ---- 3 GNN layers -------------------------------------------------------
    for (int l = 0; l < 3; l++) {
        const bool first = (l == 0);
        const int  F     = first ? FIN : HID;
        const float *Ws, *Wi, *Wj, *U, *Vw;
        if (first) { Ws = p0_Ws; Wi = p0_Wi; Wj = p0_Wj; U = p0_U; Vw = p0_V; }
        else {
            int o = (l - 1) * HID * HID;
            Ws = pl_Ws + o; Wi = pl_Wi + o; Wj = pl_Wj + o; U = pl_U + o; Vw = pl_V + o;
        }

        // XI -> sB0, XJ -> sB1 (float4 over h) ; stage Ws TRANSPOSED into sW
        {
            int k = t & 63, vg = t >> 6;
            float aI[8], aJ[8];
            #pragma unroll
            for (int j = 0; j < 8; j++) { aI[j] = 0.f; aJ[j] = 0.f; }
            for (int h = 0; h < F; h += 4) {
                float wi0 = Wi[(h    ) * HID + k], wj0 = Wj[(h    ) * HID + k];
                float wi1 = Wi[(h + 1) * HID + k], wj1 = Wj[(h + 1) * HID + k];
                float wi2 = Wi[(h + 2) * HID + k], wj2 = Wj[(h + 2) * HID + k];
                float wi3 = Wi[(h + 3) * HID + k], wj3 = Wj[(h + 3) * HID + k];
                #pragma unroll
                for (int j = 0; j < 8; j++) {
                    float4 xv = *(const float4*)&sX[(vg * 8 + j) * HID + h];
                    aI[j] = fmaf(xv.x, wi0, aI[j]);
                    aI[j] = fmaf(xv.y, wi1, aI[j]);
                    aI[j] = fmaf(xv.z, wi2, aI[j]);
                    aI[j] = fmaf(xv.w, wi3, aI[j]);
                    aJ[j] = fmaf(xv.x, wj0, aJ[j]);
                    aJ[j] = fmaf(xv.y, wj1, aJ[j]);
                    aJ[j] = fmaf(xv.z, wj2, aJ[j]);
                    aJ[j] = fmaf(xv.w, wj3, aJ[j]);
                }
            }
            #pragma unroll
            for (int j = 0; j < 8; j++) {
                sB0[(vg * 8 + j) * HID + k] = aI[j];
                sB1[(vg * 8 + j) * HID + k] = aJ[j];
            }
        }
        for (int i = t; i < F * HID; i += NT) {
            int k = i & 63, h = i >> 6;
            sW[k * WPAD + h] = Ws[h * HID + k];   // transposed stage (coalesced LDG)
        }
        __syncthreads();

        // ---- edge update: e = relu(LN(s@Ws + XI[v] + XJ[w])) ; s = e or s+e
        // warp batches NE_W edges; transposed weights -> float4 LDS.128.
        {
            float acc0[NE_W], acc1[NE_W];
            int   soff[NE_W];
            #pragma unroll
            for (int q = 0; q < NE_W; q++) {
                acc0[q] = 0.f; acc1[q] = 0.f;
                int e  = wid + q * NWARP;
                int ec = (e < ne) ? e : 0;
                soff[q] = first ? (sEfl[ec] * FIN) : (ec * HID);
            }
            const float* sbase = first ? sEmb : sS;
            const float* wrow0 = sW + lane * WPAD;
            const float* wrow1 = sW + (lane + 32) * WPAD;
            for (int h = 0; h < F; h += 4) {
                float4 w0 = *(const float4*)&wrow0[h];
                float4 w1 = *(const float4*)&wrow1[h];
                #pragma unroll
                for (int q = 0; q < NE_W; q++) {
                    float4 sv = *(const float4*)&sbase[soff[q] + h];
                    acc0[q] = fmaf(sv.x, w0.x, acc0[q]);
                    acc0[q] = fmaf(sv.y, w0.y, acc0[q]);
                    acc0[q] = fmaf(sv.z, w0.z, acc0[q]);
                    acc0[q] = fmaf(sv.w, w0.w, acc0[q]);
                    acc1[q] = fmaf(sv.x, w1.x, acc1[q]);
                    acc1[q] = fmaf(sv.y, w1.y, acc1[q]);
                    acc1[q] = fmaf(sv.z, w1.z, acc1[q]);
                    acc1[q] = fmaf(sv.w, w1.w, acc1[q]);
                }
            }
            #pragma unroll
            for (int q = 0; q < NE_W; q++) {
                int e = wid + q * NWARP;        // warp-uniform
                if (e < ne) {
                    int v = sEv[e], w = sEw[e];
                    float e0 = acc0[q] + sB0[v * HID + lane]      + sB1[w * HID + lane];
                    float e1 = acc1[q] + sB0[v * HID + lane + 32] + sB1[w * HID + lane + 32];
                    float s1 = e0 + e1, s2 = e0 * e0 + e1 * e1;
                    #pragma unroll
                    for (int o = 16; o > 0; o >>= 1) {
                        s1 += __shfl_xor_sync(0xffffffffu, s1, o);
                        s2 += __shfl_xor_sync(0xffffffffu, s2, o);
                    }
                    float mean = s1 * (1.0f / 64.0f);
                    float var  = s2 * (1.0f / 64.0f) - mean * mean;
                    float rs   = rsqrtf(var + 1e-5f);
                    float r0 = fmaxf((e0 - mean) * rs, 0.0f);
                    float r1 = fmaxf((e1 - mean) * rs, 0.0f);
                    if (!first) { r0 += sS[e * HID + lane]; r1 += sS[e * HID + lane + 32]; }
                    sS[e * HID + lane]      = r0;
                    sS[e * HID + lane + 32] = r1;
                }
            }
        }
        __syncthreads();

        // XV -> sB0, XU -> sB1 (both from old x)  (float4 over h)
        {
            int k = t & 63, vg = t >> 6;
            float aV[8], aU[8];
            #pragma unroll
            for (int j = 0; j < 8; j++) { aV[j] = 0.f; aU[j] = 0.f; }
            for (int h = 0; h < F; h += 4) {
                float wv0 = Vw[(h    ) * HID + k], wu0 = U[(h    ) * HID + k];
                float wv1 = Vw[(h + 1) * HID + k], wu1 = U[(h + 1) * HID + k];
                float wv2 = Vw[(h + 2) * HID + k], wu2 = U[(h + 2) * HID + k];
                float wv3 = Vw[(h + 3) * HID + k], wu3 = U[(h + 3) * HID + k];
                #pragma unroll
                for (int j = 0; j < 8; j++) {
                    float4 xv = *(const float4*)&sX[(vg * 8 + j) * HID + h];
                    aV[j] = fmaf(xv.x, wv0, aV[j]);
                    aV[j] = fmaf(xv.y, wv1, aV[j]);
                    aV[j] = fmaf(xv.z, wv2, aV[j]);
                    aV[j] = fmaf(xv.w, wv3, aV[j]);
                    aU[j] = fmaf(xv.x, wu0, aU[j]);
                    aU[j] = fmaf(xv.y, wu1, aU[j]);
                    aU[j] = fmaf(xv.z, wu2, aU[j]);
                    aU[j] = fmaf(xv.w, wu3, aU[j]);
                }
            }
            #pragma unroll
            for (int j = 0; j < 8; j++) {
                sB0[(vg * 8 + j) * HID + k] = aV[j];
                sB1[(vg * 8 + j) * HID + k] = aU[j];
            }
        }
        __syncthreads();

        // msg (float2 over k): sB1[v,k] += deg_inv[v]*sum_e sigm(s[e,k])*XV[w_e,k]
        {
            int kp = (t & 31) * 2;        // k pair base
            int vg = t >> 5;              // 16 groups x 4 rows
            #pragma unroll
            for (int j = 0; j < 4; j++) {
                int v = vg * 4 + j;
                float ax = 0.f, ay = 0.f;
                int eb = sOff[v], ee = sOff[v + 1];
                for (int e = eb; e < ee; e++) {
                    float2 sv = *(const float2*)&sS[e * HID + kp];
                    float2 xv = *(const float2*)&sB0[sEw[e] * HID + kp];
                    ax = fmaf(sigm(sv.x), xv.x, ax);
                    ay = fmaf(sigm(sv.y), xv.y, ay);
                }
                float di = sDi[v];
                float2* dst = (float2*)&sB1[v * HID + kp];
                float2 old = *dst;
                old.x = fmaf(ax, di, old.x);
                old.y = fmaf(ay, di, old.y);
                *dst = old;
            }
        }
        __syncthreads();

        // node update: x = (x +) relu(LN(XU + msg))
        for (int v = wid; v < VN; v += NWARP) {
            float z0 = sB1[v * HID + lane], z1 = sB1[v * HID + lane + 32];
            float s1 = z0 + z1, s2 = z0 * z0 + z1 * z1;
            #pragma unroll
            for (int o = 16; o > 0; o >>= 1) {
                s1 += __shfl_xor_sync(0xffffffffu, s1, o);
                s2 += __shfl_xor_sync(0xffffffffu, s2, o);
            }
            float mean = s1 * (1.0f / 64.0f);
            float var  = s2 * (1.0f / 64.0f) - mean * mean;
            float rs   = rsqrtf(var + 1e-5f);
            float r0 = fmaxf((z0 - mean) * rs, 0.0f);
            float r1 = fmaxf((z1 - mean) * rs, 0.0f);
            if (!first) { r0 += sX[v * HID + lane]; r1 += sX[v * HID + lane + 32]; }
            sX[v * HID + lane]      = r0;
            sX[v * HID + lane + 32] = r1;
        }
        __syncthreads();
    }

    // ---- heads --------------------------------------------------------------
    for (int i = t; i < NSW * HID; i += NT) {
        int r = i >> 6, k = i & 63;
        sSw[i] = sS[sSlot[r] * HID + k];
    }
    if (t < HID) {
        float a = 0.f;
        for (int v = 0; v < VN; v++) a += sX[v * HID + t];
        sXg[t] = a;
    }
    __syncthreads();

    // smlp hidden (10 x 256) -> reuse sS    (float2 over i)
    {
        int k = t & 255, rg = t >> 8;       // rg in {0,1}, 5 rows each
        int idxI[5], idxJ[5];
        #pragma unroll
        for (int q = 0; q < 5; q++) { idxI[q] = sSi[rg * 5 + q] * HID; idxJ[q] = sSj[rg * 5 + q] * HID; }
        float acc[5];
        #pragma unroll
        for (int q = 0; q < 5; q++) acc[q] = 0.f;
        for (int i = 0; i < 64; i += 2) {
            float w0 = sW1[i * 256 + k], w1 = sW1[(i + 1) * 256 + k];
            #pragma unroll
            for (int q = 0; q < 5; q++) {
                float2 sv = *(const float2*)&sSw[(rg * 5 + q) * HID + i];
                acc[q] = fmaf(sv.x, w0, acc[q]);
                acc[q] = fmaf(sv.y, w1, acc[q]);
            }
        }
        for (int i = 0; i < 64; i += 2) {
            float w0 = sW1[(64 + i) * 256 + k], w1 = sW1[(64 + i + 1) * 256 + k];
            #pragma unroll
            for (int q = 0; q < 5; q++) {
                float2 xv = *(const float2*)&sX[idxI[q] + i];
                acc[q] = fmaf(xv.x, w0, acc[q]);
                acc[q] = fmaf(xv.y, w1, acc[q]);
            }
        }
        for (int i = 0; i < 64; i += 2) {
            float w0 = sW1[(128 + i) * 256 + k], w1 = sW1[(128 + i + 1) * 256 + k];
            #pragma unroll
            for (int q = 0; q < 5; q++) {
                float2 xv = *(const float2*)&sX[idxJ[q] + i];
                acc[q] = fmaf(xv.x, w0, acc[q]);
                acc[q] = fmaf(xv.y, w1, acc[q]);
            }
        }
        for (int i = 0; i < 64; i += 2) {
            float w0 = sW1[(192 + i) * 256 + k], w1 = sW1[(192 + i + 1) * 256 + k];
            float2 g = *(const float2*)&sXg[i];
            #pragma unroll
            for (int q = 0; q < 5; q++) {
                acc[q] = fmaf(g.x, w0, acc[q]);
                acc[q] = fmaf(g.y, w1, acc[q]);
            }
        }
        #pragma unroll
        for (int q = 0; q < 5; q++)
            sS[(rg * 5 + q) * 256 + k] = fmaxf(acc[q], 0.0f);
    }
    __syncthreads();

    // smlp out (10x4) + cmlp graph-term g[k] (192)
    if (t < NSW * 4) {
        int r = t >> 2, j = t & 3;
        float a = 0.f;
        for (int kk = 0; kk < 256; kk++)
            a = fmaf(sS[r * 256 + kk], sW2[kk * 4 + j], a);
        sOutS[t] = sigm(a);
    }
    if (t >= 64 && t < 256) {
        int k = t - 64;
        float a = 0.f;
        for (int i = 0; i < 64; i++)
            a = fmaf(sXg[i], cW1[(128 + i) * 192 + k], a);
        sG[k] = a;
    }
    __syncthreads();

    // cmlp hidden (63 x 192) -> sHid, 4 passes of 8 rows (float2 over i)
    if (t < 384) {
        int k = t % 192, half = t / 192;
        #pragma unroll 1
        for (int p = 0; p < 4; p++) {
            int r0 = p * 16 + half * 8;
            float acc[8];
            int bA[8], bB[8];
            #pragma unroll
            for (int q = 0; q < 8; q++) {
                int r = r0 + q;
                int rr = (r < ECNT) ? r : 0;
                acc[q] = 0.f;
                bA[q] = sAi[rr] * HID;
                bB[q] = sAj[rr] * HID;
            }
            for (int i = 0; i < 64; i += 2) {
                float wa0 = cW1[i * 192 + k],        wa1 = cW1[(i + 1) * 192 + k];
                float wb0 = cW1[(64 + i) * 192 + k], wb1 = cW1[(64 + i + 1) * 192 + k];
                #pragma unroll
                for (int q = 0; q < 8; q++) {
                    float2 xa = *(const float2*)&sX[bA[q] + i];
                    float2 xb = *(const float2*)&sX[bB[q] + i];
                    acc[q] = fmaf(xa.x, wa0, acc[q]);
                    acc[q] = fmaf(xa.y, wa1, acc[q]);
                    acc[q] = fmaf(xb.x, wb0, acc[q]);
                    acc[q] = fmaf(xb.y, wb1, acc[q]);
                }
            }
            #pragma unroll
            for (int q = 0; q < 8; q++) {
                int r = r0 + q;
                if (r < ECNT)
                    sHid[r * 192 + k] = fmaxf(acc[q] + sG[k], 0.0f);
            }
        }
    }
    __syncthreads();

    // cmlp out (63x3)
    if (t < ECNT * 3) {
        int r = t / 3, j = t - r * 3;
        float a = 0.f;
        for (int kk = 0; kk < 192; kk++)
            a = fmaf(sHid[r * 192 + kk], cW2[kk * 3 + j], a);
        sOutC[t] = sigm(a);
    }
    __syncthreads();

    // per-edge parent/child voltages; zero node accumulator (reuse sXg)
    if (t < MN) {
        float o1, o2;
        if (t < ECNT) { o1 = sOutC[t * 3 + 1]; o2 = sOutC[t * 3 + 2]; }
        else          { o1 = sOutS[(t - ECNT) * 4 + 2]; o2 = sOutS[(t - ECNT) * 4 + 3]; }
        sVp[t] = 0.9f + 0.2f * o1;
        sVc[t] = 0.9f + 0.2f * o2;
    }
    if (t < VN) sXg[t] = 0.f;
    __syncthreads();

    // scatter voltages to nodes via shared atomics (Incp/Incc are one-hot)
    if (t < MN) {
        int p = (t < ECNT) ? sAi[t] : sSi[t - ECNT];
        int c = (t < ECNT) ? sAj[t] : sSj[t - ECNT];
        atomicAdd(&sXg[p], sVp[t]);
        atomicAdd(&sXg[c], sVc[t]);
    }
    __syncthreads();

    // ---- output assembly: [p_flow(73) | v(64) | graph_topo(73)] -------------
    float* ob = out + b * OUTW;
    for (int i = t; i < OUTW; i += NT) {
        float val;
        if (i < ECNT) {
            val = sOutC[i * 3] - 0.5f;
        } else if (i < MN) {
            val = sOutS[(i - ECNT) * 4 + 1] - 0.5f;
        } else if (i < MN + VN) {
            int n = i - MN;
            val = (n == 0) ? 1.0f : Dinv[n * VN + n] * sXg[n];
        } else if (i < MN + VN + ECNT) {
            val = 1.0f;
        } else {
            val = sOutS[(i - (MN + VN + ECNT)) * 4];
        }
        ob[i] = val;
    }
}

extern "C" void kernel_launch(void* const* d_in, const int* in_sizes, int n_in,
                              void* d_out, int out_size) {
    const float* x       = (const float*)d_in[0];
    const float* A       = (const float*)d_in[1];
    const float* S       = (const float*)d_in[2];
    const float* embed_s = (const float*)d_in[3];
    const float* p0_Ws   = (const float*)d_in[4];
    const float* p0_Wi   = (const float*)d_in[5];
    const float* p0_Wj   = (const float*)d_in[6];
    const float* p0_U    = (const float*)d_in[7];
    const float* p0_V    = (const float*)d_in[8];
    const float* pl_Ws   = (const float*)d_in[9];
    const float* pl_Wi   = (const float*)d_in[10];
    const float* pl_Wj   = (const float*)d_in[11];
    const float* pl_U    = (const float*)d_in[12];
    const float* pl_V    = (const float*)d_in[13];
    const float* smlp_W1 = (const float*)d_in[14];
    const float* smlp_W2 = (const float*)d_in[15];
    const float* cmlp_W1 = (const float*)d_in[16];
    const float* cmlp_W2 = (const float*)d_in[17];
    const float* Dinv    = (const float*)d_in[18];
    const float* Incp    = (const float*)d_in[19];
    const float* Incc    = (const float*)d_in[20];
    const int*   edge_A  = (const int*)d_in[21];
    const int*   edge_S  = (const int*)d_in[22];
    float*       out     = (float*)d_out;

    cudaFuncSetAttribute(gnn_kernel, cudaFuncAttributeMaxDynamicSharedMemorySize,
                         SMEM_BYTES);

    preproc_kernel<<<1, 64>>>(A, S, edge_S);
    gnn_kernel<<<BN, NT, SMEM_BYTES>>>(x, embed_s,
                                       p0_Ws, p0_Wi, p0_Wj, p0_U, p0_V,
                                       pl_Ws, pl_Wi, pl_Wj, pl_U, pl_V,
                                       smlp_W1, smlp_W2, cmlp_W1, cmlp_W2,
                                       Dinv, Incp, Incc, edge_A, edge_S, out);
}

// round 7
// speedup vs baseline: 1.5341x; 1.0909x over previous
#include <cuda_runtime.h>

#define VN   64
#define BN   200
#define NSW  10
#define ECNT 63
#define MN   73
#define FIN  32
#define HID  64
#define MAXE 146
#define NT   512
#define NWARP (NT / 32)
#define NE_W 10           // ceil(MAXE / NWARP)
#define WPAD 68           // padded transposed-weight row (float4-aligned, conflict-free)
#define OUTW (MN + VN + MN)   // 210

// ---------------- persistent topology (derived from inputs each launch) ----
__device__ int   g_ne;
__device__ int   g_ev[MAXE], g_ew[MAXE], g_efl[MAXE];
__device__ int   g_off[VN + 1];
__device__ int   g_slot[NSW];
__device__ float g_dinv[VN];

__global__ void preproc_kernel(const float* __restrict__ A,
                               const float* __restrict__ S,
                               const int*   __restrict__ edgeS) {
    __shared__ int cnt[VN];
    __shared__ int off[VN + 1];
    int v = threadIdx.x;
    if (v < VN) {
        int c = 0;
        for (int w = 0; w < VN; w++)
            if (A[v * VN + w] + S[v * VN + w] > 0.5f) c++;
        cnt[v] = c;
        g_dinv[v] = 1.0f / fmaxf((float)c, 1.0f);
    }
    __syncthreads();
    if (v == 0) {
        int s = 0;
        for (int i = 0; i < VN; i++) { off[i] = s; s += cnt[i]; }
        off[VN] = s;
        g_ne = (s > MAXE) ? MAXE : s;
    }
    __syncthreads();
    if (v < VN) {
        g_off[v] = off[v];
        if (v == 0) g_off[VN] = off[VN];
        int e = off[v];
        for (int w = 0; w < VN; w++) {
            if (A[v * VN + w] + S[v * VN + w] > 0.5f) {
                if (e < MAXE) {
                    g_ev[e]  = v;
                    g_ew[e]  = w;
                    g_efl[e] = (S[v * VN + w] > 0.5f) ? 1 : 0;
                }
                e++;
            }
        }
    }
    __syncthreads();
    if (v < NSW) {
        int si = edgeS[v], sj = edgeS[NSW + v];
        int slot = 0;
        for (int e = off[si]; e < off[si + 1]; e++)
            if (g_ew[e] == sj) slot = e;
        g_slot[v] = slot;
    }
}

// ---------------- shared memory layout (floats) ----------------------------
constexpr int O_S    = 0;
constexpr int O_X    = O_S  + MAXE * HID;       // 9344
constexpr int O_B0   = O_X  + VN * HID;         // 13440
constexpr int O_B1   = O_B0 + VN * HID;         // 17536
constexpr int O_W    = O_B1 + VN * HID;         // 21632  (transposed, 64*WPAD)
constexpr int O_XG   = O_W  + HID * WPAD;       // 25984
constexpr int O_EMB  = O_XG + HID;              // 26048
constexpr int O_SW   = O_EMB + 2 * FIN;         // 26112
constexpr int O_G    = O_SW + NSW * HID;        // 26752
constexpr int O_OUTS = O_G + 192;               // 26944
constexpr int O_OUTC = O_OUTS + 40;             // 26984
constexpr int O_VP   = O_OUTC + 192;            // 27176
constexpr int O_VC   = O_VP + 80;               // 27256
constexpr int O_DI   = O_VC + 80;               // 27336
constexpr int O_FEND = O_DI + VN;               // 27400 floats

constexpr int I_EV   = 0;
constexpr int I_EW   = I_EV + MAXE;
constexpr int I_EFL  = I_EW + MAXE;
constexpr int I_OFF  = I_EFL + MAXE;
constexpr int I_AI   = I_OFF + VN + 1 + 2;
constexpr int I_AJ   = I_AI + 64;
constexpr int I_SI   = I_AJ + 64;
constexpr int I_SJ   = I_SI + 16;
constexpr int I_SLOT = I_SJ + 16;
constexpr int I_END  = I_SLOT + 16;

constexpr int SMEM_BYTES = O_FEND * 4 + I_END * 4;   // ~112.3 KB -> 2 CTAs/SM

__device__ __forceinline__ float sigm(float z) {
    return 1.0f / (1.0f + __expf(-z));
}

// ---------------- one GNN layer (compile-time F / first) --------------------
template<int F, bool FIRST>
__device__ __forceinline__ void run_layer(
    const float* __restrict__ Ws, const float* __restrict__ Wi,
    const float* __restrict__ Wj, const float* __restrict__ U,
    const float* __restrict__ Vw,
    float* sS, float* sX, float* sB0, float* sB1, float* sW,
    const float* sEmb, const float* sDi,
    const int* sEv, const int* sEw, const int* sEfl, const int* sOff,
    int t, int lane, int wid, int ne)
{
    // ---- XI -> sB0, XJ -> sB1 (float4 over h); stage Ws TRANSPOSED into sW -
    {
        int k = t & 63, vg = t >> 6;
        float aI[8], aJ[8];
        #pragma unroll
        for (int j = 0; j < 8; j++) { aI[j] = 0.f; aJ[j] = 0.f; }
        #pragma unroll 2
        for (int h = 0; h < F; h += 4) {
            float wi0 = Wi[(h    ) * HID + k], wj0 = Wj[(h    ) * HID + k];
            float wi1 = Wi[(h + 1) * HID + k], wj1 = Wj[(h + 1) * HID + k];
            float wi2 = Wi[(h + 2) * HID + k], wj2 = Wj[(h + 2) * HID + k];
            float wi3 = Wi[(h + 3) * HID + k], wj3 = Wj[(h + 3) * HID + k];
            #pragma unroll
            for (int j = 0; j < 8; j++) {
                float4 xv = *(const float4*)&sX[(vg * 8 + j) * HID + h];
                aI[j] = fmaf(xv.x, wi0, aI[j]);
                aI[j] = fmaf(xv.y, wi1, aI[j]);
                aI[j] = fmaf(xv.z, wi2, aI[j]);
                aI[j] = fmaf(xv.w, wi3, aI[j]);
                aJ[j] = fmaf(xv.x, wj0, aJ[j]);
                aJ[j] = fmaf(xv.y, wj1, aJ[j]);
                aJ[j] = fmaf(xv.z, wj2, aJ[j]);
                aJ[j] = fmaf(xv.w, wj3, aJ[j]);
            }
        }
        #pragma unroll
        for (int j = 0; j < 8; j++) {
            sB0[(vg * 8 + j) * HID + k] = aI[j];
            sB1[(vg * 8 + j) * HID + k] = aJ[j];
        }
    }
    #pragma unroll 2
    for (int i = t; i < F * HID; i += NT) {
        int k = i & 63, h = i >> 6;
        sW[k * WPAD + h] = Ws[h * HID + k];   // transposed stage (coalesced LDG)
    }
    __syncthreads();

    // ---- edge update: e = relu(LN(s@Ws + XI[v] + XJ[w])) ; s = e or s+e ----
    {
        float acc0[NE_W], acc1[NE_W];
        int   soff[NE_W];
        #pragma unroll
        for (int q = 0; q < NE_W; q++) {
            acc0[q] = 0.f; acc1[q] = 0.f;
            int e  = wid + q * NWARP;
            int ec = (e < ne) ? e : 0;
            soff[q] = FIRST ? (sEfl[ec] * FIN) : (ec * HID);
        }
        const float* sbase = FIRST ? sEmb : sS;
        const float* wrow0 = sW + lane * WPAD;
        const float* wrow1 = sW + (lane + 32) * WPAD;
        #pragma unroll 2
        for (int h = 0; h < F; h += 4) {
            float4 w0 = *(const float4*)&wrow0[h];
            float4 w1 = *(const float4*)&wrow1[h];
            #pragma unroll
            for (int q = 0; q < NE_W; q++) {
                float4 sv = *(const float4*)&sbase[soff[q] + h];
                acc0[q] = fmaf(sv.x, w0.x, acc0[q]);
                acc0[q] = fmaf(sv.y, w0.y, acc0[q]);
                acc0[q] = fmaf(sv.z, w0.z, acc0[q]);
                acc0[q] = fmaf(sv.w, w0.w, acc0[q]);
                acc1[q] = fmaf(sv.x, w1.x, acc1[q]);
                acc1[q] = fmaf(sv.y, w1.y, acc1[q]);
                acc1[q] = fmaf(sv.z, w1.z, acc1[q]);
                acc1[q] = fmaf(sv.w, w1.w, acc1[q]);
            }
        }
        #pragma unroll
        for (int q = 0; q < NE_W; q++) {
            int e = wid + q * NWARP;        // warp-uniform
            if (e < ne) {
                int v = sEv[e], w = sEw[e];
                float e0 = acc0[q] + sB0[v * HID + lane]      + sB1[w * HID + lane];
                float e1 = acc1[q] + sB0[v * HID + lane + 32] + sB1[w * HID + lane + 32];
                float s1 = e0 + e1, s2 = e0 * e0 + e1 * e1;
                #pragma unroll
                for (int o = 16; o > 0; o >>= 1) {
                    s1 += __shfl_xor_sync(0xffffffffu, s1, o);
                    s2 += __shfl_xor_sync(0xffffffffu, s2, o);
                }
                float mean = s1 * (1.0f / 64.0f);
                float var  = s2 * (1.0f / 64.0f) - mean * mean;
                float rs   = rsqrtf(var + 1e-5f);
                float r0 = fmaxf((e0 - mean) * rs, 0.0f);
                float r1 = fmaxf((e1 - mean) * rs, 0.0f);
                if (!FIRST) { r0 += sS[e * HID + lane]; r1 += sS[e * HID + lane + 32]; }
                sS[e * HID + lane]      = r0;
                sS[e * HID + lane + 32] = r1;
            }
        }
    }
    __syncthreads();

    // ---- XV -> sB0, XU -> sB1 (both from old x)  (float4 over h) -----------
    {
        int k = t & 63, vg = t >> 6;
        float aV[8], aU[8];
        #pragma unroll
        for (int j = 0; j < 8; j++) { aV[j] = 0.f; aU[j] = 0.f; }
        #pragma unroll 2
        for (int h = 0; h < F; h += 4) {
            float wv0 = Vw[(h    ) * HID + k], wu0 = U[(h    ) * HID + k];
            float wv1 = Vw[(h + 1) * HID + k], wu1 = U[(h + 1) * HID + k];
            float wv2 = Vw[(h + 2) * HID + k], wu2 = U[(h + 2) * HID + k];
            float wv3 = Vw[(h + 3) * HID + k], wu3 = U[(h + 3) * HID + k];
            #pragma unroll
            for (int j = 0; j < 8; j++) {
                float4 xv = *(const float4*)&sX[(vg * 8 + j) * HID + h];
                aV[j] = fmaf(xv.x, wv0, aV[j]);
                aV[j] = fmaf(xv.y, wv1, aV[j]);
                aV[j] = fmaf(xv.z, wv2, aV[j]);
                aV[j] = fmaf(xv.w, wv3, aV[j]);
                aU[j] = fmaf(xv.x, wu0, aU[j]);
                aU[j] = fmaf(xv.y, wu1, aU[j]);
                aU[j] = fmaf(xv.z, wu2, aU[j]);
                aU[j] = fmaf(xv.w, wu3, aU[j]);
            }
        }
        #pragma unroll
        for (int j = 0; j < 8; j++) {
            sB0[(vg * 8 + j) * HID + k] = aV[j];
            sB1[(vg * 8 + j) * HID + k] = aU[j];
        }
    }
    __syncthreads();

    // ---- fused msg + node LN: warp-per-node -------------------------------
    // msg[v,k] = di * sum_e sigm(s[e,k]) * XV[w_e,k];  x = (x+) relu(LN(XU+msg))
    #pragma unroll
    for (int v = wid; v < VN; v += NWARP) {
        float a0 = 0.f, a1 = 0.f;
        int eb = sOff[v], ee = sOff[v + 1];
        for (int e = eb; e < ee; e++) {
            int w = sEw[e];
            a0 = fmaf(sigm(sS[e * HID + lane]),      sB0[w * HID + lane],      a0);
            a1 = fmaf(sigm(sS[e * HID + lane + 32]), sB0[w * HID + lane + 32], a1);
        }
        float di = sDi[v];
        float z0 = fmaf(a0, di, sB1[v * HID + lane]);
        float z1 = fmaf(a1, di, sB1[v * HID + lane + 32]);
        float s1 = z0 + z1, s2 = z0 * z0 + z1 * z1;
        #pragma unroll
        for (int o = 16; o > 0; o >>= 1) {
            s1 += __shfl_xor_sync(0xffffffffu, s1, o);
            s2 += __shfl_xor_sync(0xffffffffu, s2, o);
        }
        float mean = s1 * (1.0f / 64.0f);
        float var  = s2 * (1.0f / 64.0f) - mean * mean;
        float rs   = rsqrtf(var + 1e-5f);
        float r0 = fmaxf((z0 - mean) * rs, 0.0f);
        float r1 = fmaxf((z1 - mean) * rs, 0.0f);
        if (!FIRST) { r0 += sX[v * HID + lane]; r1 += sX[v * HID + lane + 32]; }
        sX[v * HID + lane]      = r0;
        sX[v * HID + lane + 32] = r1;
    }
    __syncthreads();
}

__global__ __launch_bounds__(NT, 2)
void gnn_kernel(const float* __restrict__ x_in,
                const float* __restrict__ embed_s,
                const float* __restrict__ p0_Ws, const float* __restrict__ p0_Wi,
                const float* __restrict__ p0_Wj, const float* __restrict__ p0_U,
                const float* __restrict__ p0_V,
                const float* __restrict__ pl_Ws, const float* __restrict__ pl_Wi,
                const float* __restrict__ pl_Wj, const float* __restrict__ pl_U,
                const float* __restrict__ pl_V,
                const float* __restrict__ sW1,  const float* __restrict__ sW2,
                const float* __restrict__ cW1,  const float* __restrict__ cW2,
                const float* __restrict__ Dinv, const float* __restrict__ Incp,
                const float* __restrict__ Incc,
                const int*   __restrict__ edgeA, const int* __restrict__ edgeS,
                float* __restrict__ out) {
    extern __shared__ float smf[];
    float* sS   = smf + O_S;
    float* sX   = smf + O_X;
    float* sB0  = smf + O_B0;
    float* sB1  = smf + O_B1;
    float* sW   = smf + O_W;
    float* sXg  = smf + O_XG;
    float* sEmb = smf + O_EMB;
    float* sSw  = smf + O_SW;
    float* sG   = smf + O_G;
    float* sOutS= smf + O_OUTS;
    float* sOutC= smf + O_OUTC;
    float* sVp  = smf + O_VP;
    float* sVc  = smf + O_VC;
    float* sDi  = smf + O_DI;
    int*   smi  = (int*)(smf + O_FEND);
    int* sEv = smi + I_EV;  int* sEw = smi + I_EW;  int* sEfl = smi + I_EFL;
    int* sOff= smi + I_OFF; int* sAi = smi + I_AI;  int* sAj  = smi + I_AJ;
    int* sSi = smi + I_SI;  int* sSj = smi + I_SJ;  int* sSlot= smi + I_SLOT;
    float* sHid = smf + O_B0;   // 63*192 = 12096 <= 12544 contiguous (B0,B1,W)

    const int t    = threadIdx.x;
    const int b    = blockIdx.x;
    const int lane = t & 31;
    const int wid  = t >> 5;
    const int ne   = g_ne;

    // ---- load per-batch x (float4) and topology into shared -----------------
    {
        const float4* xi4 = (const float4*)(x_in + b * VN * FIN);
        int v = t >> 3, h = (t & 7) * 4;          // 512 float4 = whole tile
        *(float4*)&sX[v * HID + h] = xi4[t];
    }
    for (int i = t; i < ne; i += NT) {
        sEv[i] = g_ev[i]; sEw[i] = g_ew[i]; sEfl[i] = g_efl[i];
    }
    if (t <= VN) sOff[t] = g_off[t];
    if (t < VN)  { sDi[t] = g_dinv[t]; sEmb[t] = embed_s[t]; }
    if (t < ECNT){ sAi[t] = edgeA[t]; sAj[t] = edgeA[ECNT + t]; }
    if (t < NSW) { sSi[t] = edgeS[t]; sSj[t] = edgeS[NSW + t]; sSlot[t] = g_slot[t]; }
    __syncthreads();

    // ---- 3 GNN layers (compile-time specialized) ----------------------------
    run_layer<FIN, true>(p0_Ws, p0_Wi, p0_Wj, p0_U, p0_V,
                         sS, sX, sB0, sB1, sW, sEmb, sDi,
                         sEv, sEw, sEfl, sOff, t, lane, wid, ne);
    run_layer<HID, false>(pl_Ws, pl_Wi, pl_Wj, pl_U, pl_V,
                          sS, sX, sB0, sB1, sW, sEmb, sDi,
                          sEv, sEw, sEfl, sOff, t, lane, wid, ne);
    run_layer<HID, false>(pl_Ws + HID * HID, pl_Wi + HID * HID,
                          pl_Wj + HID * HID, pl_U + HID * HID, pl_V + HID * HID,
                          sS, sX, sB0, sB1, sW, sEmb, sDi,
                          sEv, sEw, sEfl, sOff, t, lane, wid, ne);

    // ---- heads --------------------------------------------------------------
    for (int i = t; i < NSW * HID; i += NT) {
        int r = i >> 6, k = i & 63;
        sSw[i] = sS[sSlot[r] * HID + k];
    }
    if (t < HID) {
        float a = 0.f;
        #pragma unroll 4
        for (int v = 0; v < VN; v++) a += sX[v * HID + t];
        sXg[t] = a;
    }
    __syncthreads();

    // smlp hidden (10 x 256) -> reuse sS    (float4 over i)
    {
        int k = t & 255, rg = t >> 8;       // rg in {0,1}, 5 rows each
        int idxI[5], idxJ[5];
        #pragma unroll
        for (int q = 0; q < 5; q++) { idxI[q] = sSi[rg * 5 + q] * HID; idxJ[q] = sSj[rg * 5 + q] * HID; }
        float acc[5];
        #pragma unroll
        for (int q = 0; q < 5; q++) acc[q] = 0.f;
        #pragma unroll 2
        for (int i = 0; i < 64; i += 4) {
            float w0 = sW1[(i    ) * 256 + k], w1 = sW1[(i + 1) * 256 + k];
            float w2 = sW1[(i + 2) * 256 + k], w3 = sW1[(i + 3) * 256 + k];
            #pragma unroll
            for (int q = 0; q < 5; q++) {
                float4 sv = *(const float4*)&sSw[(rg * 5 + q) * HID + i];
                acc[q] = fmaf(sv.x, w0, acc[q]);
                acc[q] = fmaf(sv.y, w1, acc[q]);
                acc[q] = fmaf(sv.z, w2, acc[q]);
                acc[q] = fmaf(sv.w, w3, acc[q]);
            }
        }
        #pragma unroll 2
        for (int i = 0; i < 64; i += 4) {
            float w0 = sW1[(64 + i    ) * 256 + k], w1 = sW1[(64 + i + 1) * 256 + k];
            float w2 = sW1[(64 + i + 2) * 256 + k], w3 = sW1[(64 + i + 3) * 256 + k];
            #pragma unroll
            for (int q = 0; q < 5; q++) {
                float4 xv = *(const float4*)&sX[idxI[q] + i];
                acc[q] = fmaf(xv.x, w0, acc[q]);
                acc[q] = fmaf(xv.y, w1, acc[q]);
                acc[q] = fmaf(xv.z, w2, acc[q]);
                acc[q] = fmaf(xv.w, w3, acc[q]);
            }
        }
        #pragma unroll 2
        for (int i = 0; i < 64; i += 4) {
            float w0 = sW1[(128 + i    ) * 256 + k], w1 = sW1[(128 + i + 1) * 256 + k];
            float w2 = sW1[(128 + i + 2) * 256 + k], w3 = sW1[(128 + i + 3) * 256 + k];
            #pragma unroll
            for (int q = 0; q < 5; q++) {
                float4 xv = *(const float4*)&sX[idxJ[q] + i];
                acc[q] = fmaf(xv.x, w0, acc[q]);
                acc[q] = fmaf(xv.y, w1, acc[q]);
                acc[q] = fmaf(xv.z, w2, acc[q]);
                acc[q] = fmaf(xv.w, w3, acc[q]);
            }
        }
        #pragma unroll 2
        for (int i = 0; i < 64; i += 4) {
            float w0 = sW1[(192 + i    ) * 256 + k], w1 = sW1[(192 + i + 1) * 256 + k];
            float w2 = sW1[(192 + i + 2) * 256 + k], w3 = sW1[(192 + i + 3) * 256 + k];
            float4 g = *(const float4*)&sXg[i];
            #pragma unroll
            for (int q = 0; q < 5; q++) {
                acc[q] = fmaf(g.x, w0, acc[q]);
                acc[q] = fmaf(g.y, w1, acc[q]);
                acc[q] = fmaf(g.z, w2, acc[q]);
                acc[q] = fmaf(g.w, w3, acc[q]);
            }
        }
        #pragma unroll
        for (int q = 0; q < 5; q++)
            sS[(rg * 5 + q) * 256 + k] = fmaxf(acc[q], 0.0f);
    }
    __syncthreads();

    // smlp out (warps 8-15, 5 outputs each, lane-split dot) +
    // cmlp graph-term g[k] (threads 64..255)
    if (wid >= 8) {
        int w8 = wid - 8;
        #pragma unroll
        for (int q = 0; q < 5; q++) {
            int o = w8 * 5 + q;               // o in [0,40)
            int r = o >> 2, j = o & 3;
            float a = 0.f;
            #pragma unroll
            for (int kk = 0; kk < 256; kk += 32)
                a = fmaf(sS[r * 256 + kk + lane], sW2[(kk + lane) * 4 + j], a);
            #pragma unroll
            for (int off = 16; off > 0; off >>= 1)
                a += __shfl_xor_sync(0xffffffffu, a, off);
            if (lane == 0) sOutS[o] = sigm(a);
        }
    } else if (t >= 64 && t < 256) {
        int k = t - 64;
        float a = 0.f;
        #pragma unroll 4
        for (int i = 0; i < 64; i++)
            a = fmaf(sXg[i], cW1[(128 + i) * 192 + k], a);
        sG[k] = a;
    }
    __syncthreads();

    // cmlp hidden (63 x 192) -> sHid, 4 passes of 8 rows (float4 over i)
    if (t < 384) {
        int k = t % 192, half = t / 192;
        #pragma unroll 1
        for (int p = 0; p < 4; p++) {
            int r0 = p * 16 + half * 8;
            float acc[8];
            int bA[8], bB[8];
            #pragma unroll
            for (int q = 0; q < 8; q++) {
                int r = r0 + q;
                int rr = (r < ECNT) ? r : 0;
                acc[q] = 0.f;
                bA[q] = sAi[rr] * HID;
                bB[q] = sAj[rr] * HID;
            }
            #pragma unroll 2
            for (int i = 0; i < 64; i += 4) {
                float wa0 = cW1[(i    ) * 192 + k], wa1 = cW1[(i + 1) * 192 + k];
                float wa2 = cW1[(i + 2) * 192 + k], wa3 = cW1[(i + 3) * 192 + k];
                float wb0 = cW1[(64 + i    ) * 192 + k], wb1 = cW1[(64 + i + 1) * 192 + k];
                float wb2 = cW1[(64 + i + 2) * 192 + k], wb3 = cW1[(64 + i + 3) * 192 + k];
                #pragma unroll
                for (int q = 0; q < 8; q++) {
                    float4 xa = *(const float4*)&sX[bA[q] + i];
                    float4 xb = *(const float4*)&sX[bB[q] + i];
                    acc[q] = fmaf(xa.x, wa0, acc[q]);
                    acc[q] = fmaf(xa.y, wa1, acc[q]);
                    acc[q] = fmaf(xa.z, wa2, acc[q]);
                    acc[q] = fmaf(xa.w, wa3, acc[q]);
                    acc[q] = fmaf(xb.x, wb0, acc[q]);
                    acc[q] = fmaf(xb.y, wb1, acc[q]);
                    acc[q] = fmaf(xb.z, wb2, acc[q]);
                    acc[q] = fmaf(xb.w, wb3, acc[q]);
                }
            }
            #pragma unroll
            for (int q = 0; q < 8; q++) {
                int r = r0 + q;
                if (r < ECNT)
                    sHid[r * 192 + k] = fmaxf(acc[q] + sG[k], 0.0f);
            }
        }
    }
    __syncthreads();

    // cmlp out (63x3 = 189 outputs, one per warp-iteration, lane-split dot)
    for (int o = wid; o < ECNT * 3; o += NWARP) {
        int r = o / 3, j = o - r * 3;
        float a = 0.f;
        #pragma unroll
        for (int kk = 0; kk < 192; kk += 32)
            a = fmaf(sHid[r * 192 + kk + lane], cW2[(kk + lane) * 3 + j], a);
        #pragma unroll
        for (int off = 16; off > 0; off >>= 1)
            a += __shfl_xor_sync(0xffffffffu, a, off);
        if (lane == 0) sOutC[o] = sigm(a);
    }
    __syncthreads();

    // per-edge parent/child voltages; zero node accumulator (reuse sXg)
    if (t < MN) {
        float o1, o2;
        if (t < ECNT) { o1 = sOutC[t * 3 + 1]; o2 = sOutC[t * 3 + 2]; }
        else          { o1 = sOutS[(t - ECNT) * 4 + 2]; o2 = sOutS[(t - ECNT) * 4 + 3]; }
        sVp[t] = 0.9f + 0.2f * o1;
        sVc[t] = 0.9f + 0.2f * o2;
    }
    if (t < VN) sXg[t] = 0.f;
    __syncthreads();

    // scatter voltages to nodes via shared atomics (Incp/Incc are one-hot)
    if (t < MN) {
        int p = (t < ECNT) ? sAi[t] : sSi[t - ECNT];
        int c = (t < ECNT) ? sAj[t] : sSj[t - ECNT];
        atomicAdd(&sXg[p], sVp[t]);
        atomicAdd(&sXg[c], sVc[t]);
    }
    __syncthreads();

    // ---- output assembly: [p_flow(73) | v(64) | graph_topo(73)] -------------
    float* ob = out + b * OUTW;
    for (int i = t; i < OUTW; i += NT) {
        float val;
        if (i < ECNT) {
            val = sOutC[i * 3] - 0.5f;
        } else if (i < MN) {
            val = sOutS[(i - ECNT) * 4 + 1] - 0.5f;
        } else if (i < MN + VN) {
            int n = i - MN;
            val = (n == 0) ? 1.0f : Dinv[n * VN + n] * sXg[n];
        } else if (i < MN + VN + ECNT) {
            val = 1.0f;
        } else {
            val = sOutS[(i - (MN + VN + ECNT)) * 4];
        }
        ob[i] = val;
    }
}

extern "C" void kernel_launch(void* const* d_in, const int* in_sizes, int n_in,
                              void* d_out, int out_size) {
    const float* x       = (const float*)d_in[0];
    const float* A       = (const float*)d_in[1];
    const float* S       = (const float*)d_in[2];
    const float* embed_s = (const float*)d_in[3];
    const float* p0_Ws   = (const float*)d_in[4];
    const float* p0_Wi   = (const float*)d_in[5];
    const float* p0_Wj   = (const float*)d_in[6];
    const float* p0_U    = (const float*)d_in[7];
    const float* p0_V    = (const float*)d_in[8];
    const float* pl_Ws   = (const float*)d_in[9];
    const float* pl_Wi   = (const float*)d_in[10];
    const float* pl_Wj   = (const float*)d_in[11];
    const float* pl_U    = (const float*)d_in[12];
    const float* pl_V    = (const float*)d_in[13];
    const float* smlp_W1 = (const float*)d_in[14];
    const float* smlp_W2 = (const float*)d_in[15];
    const float* cmlp_W1 = (const float*)d_in[16];
    const float* cmlp_W2 = (const float*)d_in[17];
    const float* Dinv    = (const float*)d_in[18];
    const float* Incp    = (const float*)d_in[19];
    const float* Incc    = (const float*)d_in[20];
    const int*   edge_A  = (const int*)d_in[21];
    const int*   edge_S  = (const int*)d_in[22];
    float*       out     = (float*)d_out;

    cudaFuncSetAttribute(gnn_kernel, cudaFuncAttributeMaxDynamicSharedMemorySize,
                         SMEM_BYTES);

    preproc_kernel<<<1, 64>>>(A, S, edge_S);
    gnn_kernel<<<BN, NT, SMEM_BYTES>>>(x, embed_s,
                                       p0_Ws, p0_Wi, p0_Wj, p0_U, p0_V,
                                       pl_Ws, pl_Wi, pl_Wj, pl_U, pl_V,
                                       smlp_W1, smlp_W2, cmlp_W1, cmlp_W2,
                                       Dinv, Incp, Incc, edge_A, edge_S, out);
}

// round 8
// speedup vs baseline: 1.5540x; 1.0130x over previous
#include <cuda_runtime.h>

#define VN   64
#define BN   200
#define NSW  10
#define ECNT 63
#define MN   73
#define FIN  32
#define HID  64
#define MAXE 146
#define NT   512
#define NWARP (NT / 32)
#define NE_W 10           // ceil(MAXE / NWARP)
#define WPAD 68           // padded transposed-weight row (float4-aligned, conflict-free)
#define OUTW (MN + VN + MN)   // 210

// ---------------- persistent topology (derived from inputs each launch) ----
__device__ int   g_ne;
__device__ int   g_ev[MAXE], g_ew[MAXE], g_efl[MAXE];
__device__ int   g_off[VN + 1];
__device__ int   g_slot[NSW];
__device__ float g_dinv[VN];

__global__ void preproc_kernel(const float* __restrict__ A,
                               const float* __restrict__ S,
                               const int*   __restrict__ edgeS) {
    __shared__ int cnt[VN];
    __shared__ int off[VN + 1];
    int v = threadIdx.x;
    if (v < VN) {
        int c = 0;
        for (int w = 0; w < VN; w++)
            if (A[v * VN + w] + S[v * VN + w] > 0.5f) c++;
        cnt[v] = c;
        g_dinv[v] = 1.0f / fmaxf((float)c, 1.0f);
    }
    __syncthreads();
    if (v == 0) {
        int s = 0;
        for (int i = 0; i < VN; i++) { off[i] = s; s += cnt[i]; }
        off[VN] = s;
        g_ne = (s > MAXE) ? MAXE : s;
    }
    __syncthreads();
    if (v < VN) {
        g_off[v] = off[v];
        if (v == 0) g_off[VN] = off[VN];
        int e = off[v];
        for (int w = 0; w < VN; w++) {
            if (A[v * VN + w] + S[v * VN + w] > 0.5f) {
                if (e < MAXE) {
                    g_ev[e]  = v;
                    g_ew[e]  = w;
                    g_efl[e] = (S[v * VN + w] > 0.5f) ? 1 : 0;
                }
                e++;
            }
        }
    }
    __syncthreads();
    if (v < NSW) {
        int si = edgeS[v], sj = edgeS[NSW + v];
        int slot = 0;
        for (int e = off[si]; e < off[si + 1]; e++)
            if (g_ew[e] == sj) slot = e;
        g_slot[v] = slot;
    }
}

// ---------------- shared memory layout (floats) ----------------------------
constexpr int O_S    = 0;
constexpr int O_X    = O_S  + MAXE * HID;       // 9344
constexpr int O_B0   = O_X  + VN * HID;         // 13440
constexpr int O_B1   = O_B0 + VN * HID;         // 17536
constexpr int O_W    = O_B1 + VN * HID;         // 21632  (transposed, 64*WPAD)
constexpr int O_XG   = O_W  + HID * WPAD;       // 25984
constexpr int O_EMB  = O_XG + HID;              // 26048
constexpr int O_SW   = O_EMB + 2 * FIN;         // 26112
constexpr int O_G    = O_SW + NSW * HID;        // 26752
constexpr int O_OUTS = O_G + 192;               // 26944
constexpr int O_OUTC = O_OUTS + 40;             // 26984
constexpr int O_VP   = O_OUTC + 192;            // 27176
constexpr int O_VC   = O_VP + 80;               // 27256
constexpr int O_DI   = O_VC + 80;               // 27336
constexpr int O_FEND = O_DI + VN;               // 27400 floats

constexpr int I_EV   = 0;
constexpr int I_EW   = I_EV + MAXE;
constexpr int I_EFL  = I_EW + MAXE;
constexpr int I_OFF  = I_EFL + MAXE;
constexpr int I_AI   = I_OFF + VN + 1 + 2;
constexpr int I_AJ   = I_AI + 64;
constexpr int I_SI   = I_AJ + 64;
constexpr int I_SJ   = I_SI + 16;
constexpr int I_SLOT = I_SJ + 16;
constexpr int I_END  = I_SLOT + 16;

constexpr int SMEM_BYTES = O_FEND * 4 + I_END * 4;   // ~112.3 KB -> 2 CTAs/SM

__device__ __forceinline__ float sigm(float z) {
    return 1.0f / (1.0f + __expf(-z));
}

// ---------------- one GNN layer (compile-time F / first) --------------------
// All five weight matrices are staged through shared memory (sW / sB1) so the
// hot GEMM loops never touch the L2-latency global path.
template<int F, bool FIRST>
__device__ __forceinline__ void run_layer(
    const float* __restrict__ Ws, const float* __restrict__ Wi,
    const float* __restrict__ Wj, const float* __restrict__ U,
    const float* __restrict__ Vw,
    float* sS, float* sX, float* sB0, float* sB1, float* sW,
    const float* sEmb, const float* sDi,
    const int* sEv, const int* sEw, const int* sEfl, const int* sOff,
    int t, int lane, int wid, int ne)
{
    // ---- stage Wi -> sW (plain), Wj -> sB1 ---------------------------------
    #pragma unroll
    for (int i = t; i < F * HID; i += NT) {
        sW[i]  = Wi[i];
        sB1[i] = Wj[i];
    }
    __syncthreads();

    // ---- XI -> sB0 (write now), XJ -> regs (write after barrier) -----------
    int k = t & 63, vg = t >> 6;
    float aJ[8];
    {
        float aI[8];
        #pragma unroll
        for (int j = 0; j < 8; j++) { aI[j] = 0.f; aJ[j] = 0.f; }
        #pragma unroll 4
        for (int h = 0; h < F; h += 4) {
            float wi0 = sW[(h    ) * HID + k], wj0 = sB1[(h    ) * HID + k];
            float wi1 = sW[(h + 1) * HID + k], wj1 = sB1[(h + 1) * HID + k];
            float wi2 = sW[(h + 2) * HID + k], wj2 = sB1[(h + 2) * HID + k];
            float wi3 = sW[(h + 3) * HID + k], wj3 = sB1[(h + 3) * HID + k];
            #pragma unroll
            for (int j = 0; j < 8; j++) {
                float4 xv = *(const float4*)&sX[(vg * 8 + j) * HID + h];
                aI[j] = fmaf(xv.x, wi0, aI[j]);
                aI[j] = fmaf(xv.y, wi1, aI[j]);
                aI[j] = fmaf(xv.z, wi2, aI[j]);
                aI[j] = fmaf(xv.w, wi3, aI[j]);
                aJ[j] = fmaf(xv.x, wj0, aJ[j]);
                aJ[j] = fmaf(xv.y, wj1, aJ[j]);
                aJ[j] = fmaf(xv.z, wj2, aJ[j]);
                aJ[j] = fmaf(xv.w, wj3, aJ[j]);
            }
        }
        #pragma unroll
        for (int j = 0; j < 8; j++)
            sB0[(vg * 8 + j) * HID + k] = aI[j];   // sB0 has no readers yet
    }
    __syncthreads();            // all reads of sW(Wi)/sB1(Wj) complete

    // ---- write XJ; stage Ws transposed into sW ------------------------------
    #pragma unroll
    for (int j = 0; j < 8; j++)
        sB1[(vg * 8 + j) * HID + k] = aJ[j];
    #pragma unroll
    for (int i = t; i < F * HID; i += NT) {
        int kk = i & 63, h = i >> 6;
        sW[kk * WPAD + h] = Ws[h * HID + kk];   // transposed stage
    }
    __syncthreads();

    // ---- edge update: e = relu(LN(s@Ws + XI[v] + XJ[w])) ; s = e or s+e ----
    {
        float acc0[NE_W], acc1[NE_W];
        int   soff[NE_W];
        #pragma unroll
        for (int q = 0; q < NE_W; q++) {
            acc0[q] = 0.f; acc1[q] = 0.f;
            int e  = wid + q * NWARP;
            int ec = (e < ne) ? e : 0;
            soff[q] = FIRST ? (sEfl[ec] * FIN) : (ec * HID);
        }
        const float* sbase = FIRST ? sEmb : sS;
        const float* wrow0 = sW + lane * WPAD;
        const float* wrow1 = sW + (lane + 32) * WPAD;
        #pragma unroll 2
        for (int h = 0; h < F; h += 4) {
            float4 w0 = *(const float4*)&wrow0[h];
            float4 w1 = *(const float4*)&wrow1[h];
            #pragma unroll
            for (int q = 0; q < NE_W; q++) {
                float4 sv = *(const float4*)&sbase[soff[q] + h];
                acc0[q] = fmaf(sv.x, w0.x, acc0[q]);
                acc0[q] = fmaf(sv.y, w0.y, acc0[q]);
                acc0[q] = fmaf(sv.z, w0.z, acc0[q]);
                acc0[q] = fmaf(sv.w, w0.w, acc0[q]);
                acc1[q] = fmaf(sv.x, w1.x, acc1[q]);
                acc1[q] = fmaf(sv.y, w1.y, acc1[q]);
                acc1[q] = fmaf(sv.z, w1.z, acc1[q]);
                acc1[q] = fmaf(sv.w, w1.w, acc1[q]);
            }
        }
        #pragma unroll
        for (int q = 0; q < NE_W; q++) {
            int e = wid + q * NWARP;        // warp-uniform
            if (e < ne) {
                int v = sEv[e], w = sEw[e];
                float e0 = acc0[q] + sB0[v * HID + lane]      + sB1[w * HID + lane];
                float e1 = acc1[q] + sB0[v * HID + lane + 32] + sB1[w * HID + lane + 32];
                float s1 = e0 + e1, s2 = e0 * e0 + e1 * e1;
                #pragma unroll
                for (int o = 16; o > 0; o >>= 1) {
                    s1 += __shfl_xor_sync(0xffffffffu, s1, o);
                    s2 += __shfl_xor_sync(0xffffffffu, s2, o);
                }
                float mean = s1 * (1.0f / 64.0f);
                float var  = s2 * (1.0f / 64.0f) - mean * mean;
                float rs   = rsqrtf(var + 1e-5f);
                float r0 = fmaxf((e0 - mean) * rs, 0.0f);
                float r1 = fmaxf((e1 - mean) * rs, 0.0f);
                if (!FIRST) { r0 += sS[e * HID + lane]; r1 += sS[e * HID + lane + 32]; }
                sS[e * HID + lane]      = r0;
                sS[e * HID + lane + 32] = r1;
            }
        }
    }
    __syncthreads();

    // ---- stage Vw -> sW (plain), U -> sB1 (XI/XJ now dead) ------------------
    #pragma unroll
    for (int i = t; i < F * HID; i += NT) {
        sW[i]  = Vw[i];
        sB1[i] = U[i];
    }
    __syncthreads();

    // ---- XV -> sB0 (write now), XU -> regs ----------------------------------
    float aU[8];
    {
        float aV[8];
        #pragma unroll
        for (int j = 0; j < 8; j++) { aV[j] = 0.f; aU[j] = 0.f; }
        #pragma unroll 4
        for (int h = 0; h < F; h += 4) {
            float wv0 = sW[(h    ) * HID + k], wu0 = sB1[(h    ) * HID + k];
            float wv1 = sW[(h + 1) * HID + k], wu1 = sB1[(h + 1) * HID + k];
            float wv2 = sW[(h + 2) * HID + k], wu2 = sB1[(h + 2) * HID + k];
            float wv3 = sW[(h + 3) * HID + k], wu3 = sB1[(h + 3) * HID + k];
            #pragma unroll
            for (int j = 0; j < 8; j++) {
                float4 xv = *(const float4*)&sX[(vg * 8 + j) * HID + h];
                aV[j] = fmaf(xv.x, wv0, aV[j]);
                aV[j] = fmaf(xv.y, wv1, aV[j]);
                aV[j] = fmaf(xv.z, wv2, aV[j]);
                aV[j] = fmaf(xv.w, wv3, aV[j]);
                aU[j] = fmaf(xv.x, wu0, aU[j]);
                aU[j] = fmaf(xv.y, wu1, aU[j]);
                aU[j] = fmaf(xv.z, wu2, aU[j]);
                aU[j] = fmaf(xv.w, wu3, aU[j]);
            }
        }
        #pragma unroll
        for (int j = 0; j < 8; j++)
            sB0[(vg * 8 + j) * HID + k] = aV[j];   // XI dead, safe
    }
    __syncthreads();            // all reads of sW(Vw)/sB1(U) complete

    #pragma unroll
    for (int j = 0; j < 8; j++)
        sB1[(vg * 8 + j) * HID + k] = aU[j];
    __syncthreads();

    // ---- fused msg + node LN: warp-per-node ---------------------------------
    #pragma unroll
    for (int v = wid; v < VN; v += NWARP) {
        float a0 = 0.f, a1 = 0.f;
        int eb = sOff[v], ee = sOff[v + 1];
        for (int e = eb; e < ee; e++) {
            int w = sEw[e];
            a0 = fmaf(sigm(sS[e * HID + lane]),      sB0[w * HID + lane],      a0);
            a1 = fmaf(sigm(sS[e * HID + lane + 32]), sB0[w * HID + lane + 32], a1);
        }
        float di = sDi[v];
        float z0 = fmaf(a0, di, sB1[v * HID + lane]);
        float z1 = fmaf(a1, di, sB1[v * HID + lane + 32]);
        float s1 = z0 + z1, s2 = z0 * z0 + z1 * z1;
        #pragma unroll
        for (int o = 16; o > 0; o >>= 1) {
            s1 += __shfl_xor_sync(0xffffffffu, s1, o);
            s2 += __shfl_xor_sync(0xffffffffu, s2, o);
        }
        float mean = s1 * (1.0f / 64.0f);
        float var  = s2 * (1.0f / 64.0f) - mean * mean;
        float rs   = rsqrtf(var + 1e-5f);
        float r0 = fmaxf((z0 - mean) * rs, 0.0f);
        float r1 = fmaxf((z1 - mean) * rs, 0.0f);
        if (!FIRST) { r0 += sX[v * HID + lane]; r1 += sX[v * HID + lane + 32]; }
        sX[v * HID + lane]      = r0;
        sX[v * HID + lane + 32] = r1;
    }
    __syncthreads();
}

__global__ __launch_bounds__(NT, 2)
void gnn_kernel(const float* __restrict__ x_in,
                const float* __restrict__ embed_s,
                const float* __restrict__ p0_Ws, const float* __restrict__ p0_Wi,
                const float* __restrict__ p0_Wj, const float* __restrict__ p0_U,
                const float* __restrict__ p0_V,
                const float* __restrict__ pl_Ws, const float* __restrict__ pl_Wi,
                const float* __restrict__ pl_Wj, const float* __restrict__ pl_U,
                const float* __restrict__ pl_V,
                const float* __restrict__ sW1,  const float* __restrict__ sW2,
                const float* __restrict__ cW1,  const float* __restrict__ cW2,
                const float* __restrict__ Dinv, const float* __restrict__ Incp,
                const float* __restrict__ Incc,
                const int*   __restrict__ edgeA, const int* __restrict__ edgeS,
                float* __restrict__ out) {
    extern __shared__ float smf[];
    float* sS   = smf + O_S;
    float* sX   = smf + O_X;
    float* sB0  = smf + O_B0;
    float* sB1  = smf + O_B1;
    float* sW   = smf + O_W;
    float* sXg  = smf + O_XG;
    float* sEmb = smf + O_EMB;
    float* sSw  = smf + O_SW;
    float* sG   = smf + O_G;
    float* sOutS= smf + O_OUTS;
    float* sOutC= smf + O_OUTC;
    float* sVp  = smf + O_VP;
    float* sVc  = smf + O_VC;
    float* sDi  = smf + O_DI;
    int*   smi  = (int*)(smf + O_FEND);
    int* sEv = smi + I_EV;  int* sEw = smi + I_EW;  int* sEfl = smi + I_EFL;
    int* sOff= smi + I_OFF; int* sAi = smi + I_AI;  int* sAj  = smi + I_AJ;
    int* sSi = smi + I_SI;  int* sSj = smi + I_SJ;  int* sSlot= smi + I_SLOT;
    float* sHid = smf + O_B0;   // 63*192 = 12096 <= 12544 contiguous (B0,B1,W)

    const int t    = threadIdx.x;
    const int b    = blockIdx.x;
    const int lane = t & 31;
    const int wid  = t >> 5;
    const int ne   = g_ne;

    // ---- load per-batch x (float4) and topology into shared -----------------
    {
        const float4* xi4 = (const float4*)(x_in + b * VN * FIN);
        int v = t >> 3, h = (t & 7) * 4;          // 512 float4 = whole tile
        *(float4*)&sX[v * HID + h] = xi4[t];
    }
    for (int i = t; i < ne; i += NT) {
        sEv[i] = g_ev[i]; sEw[i] = g_ew[i]; sEfl[i] = g_efl[i];
    }
    if (t <= VN) sOff[t] = g_off[t];
    if (t < VN)  { sDi[t] = g_dinv[t]; sEmb[t] = embed_s[t]; }
    if (t < ECNT){ sAi[t] = edgeA[t]; sAj[t] = edgeA[ECNT + t]; }
    if (t < NSW) { sSi[t] = edgeS[t]; sSj[t] = edgeS[NSW + t]; sSlot[t] = g_slot[t]; }
    __syncthreads();

    // ---- 3 GNN layers (compile-time specialized) ----------------------------
    run_layer<FIN, true>(p0_Ws, p0_Wi, p0_Wj, p0_U, p0_V,
                         sS, sX, sB0, sB1, sW, sEmb, sDi,
                         sEv, sEw, sEfl, sOff, t, lane, wid, ne);
    run_layer<HID, false>(pl_Ws, pl_Wi, pl_Wj, pl_U, pl_V,
                          sS, sX, sB0, sB1, sW, sEmb, sDi,
                          sEv, sEw, sEfl, sOff, t, lane, wid, ne);
    run_layer<HID, false>(pl_Ws + HID * HID, pl_Wi + HID * HID,
                          pl_Wj + HID * HID, pl_U + HID * HID, pl_V + HID * HID,
                          sS, sX, sB0, sB1, sW, sEmb, sDi,
                          sEv, sEw, sEfl, sOff, t, lane, wid, ne);

    // ---- heads --------------------------------------------------------------
    for (int i = t; i < NSW * HID; i += NT) {
        int r = i >> 6, k = i & 63;
        sSw[i] = sS[sSlot[r] * HID + k];
    }
    if (t < HID) {
        float a = 0.f;
        #pragma unroll 4
        for (int v = 0; v < VN; v++) a += sX[v * HID + t];
        sXg[t] = a;
    }
    __syncthreads();

    // smlp hidden (10 x 256) -> reuse sS    (float4 over i)
    {
        int k = t & 255, rg = t >> 8;       // rg in {0,1}, 5 rows each
        int idxI[5], idxJ[5];
        #pragma unroll
        for (int q = 0; q < 5; q++) { idxI[q] = sSi[rg * 5 + q] * HID; idxJ[q] = sSj[rg * 5 + q] * HID; }
        float acc[5];
        #pragma unroll
        for (int q = 0; q < 5; q++) acc[q] = 0.f;
        #pragma unroll 2
        for (int i = 0; i < 64; i += 4) {
            float w0 = sW1[(i    ) * 256 + k], w1 = sW1[(i + 1) * 256 + k];
            float w2 = sW1[(i + 2) * 256 + k], w3 = sW1[(i + 3) * 256 + k];
            #pragma unroll
            for (int q = 0; q < 5; q++) {
                float4 sv = *(const float4*)&sSw[(rg * 5 + q) * HID + i];
                acc[q] = fmaf(sv.x, w0, acc[q]);
                acc[q] = fmaf(sv.y, w1, acc[q]);
                acc[q] = fmaf(sv.z, w2, acc[q]);
                acc[q] = fmaf(sv.w, w3, acc[q]);
            }
        }
        #pragma unroll 2
        for (int i = 0; i < 64; i += 4) {
            float w0 = sW1[(64 + i    ) * 256 + k], w1 = sW1[(64 + i + 1) * 256 + k];
            float w2 = sW1[(64 + i + 2) * 256 + k], w3 = sW1[(64 + i + 3) * 256 + k];
            #pragma unroll
            for (int q = 0; q < 5; q++) {
                float4 xv = *(const float4*)&sX[idxI[q] + i];
                acc[q] = fmaf(xv.x, w0, acc[q]);
                acc[q] = fmaf(xv.y, w1, acc[q]);
                acc[q] = fmaf(xv.z, w2, acc[q]);
                acc[q] = fmaf(xv.w, w3, acc[q]);
            }
        }
        #pragma unroll 2
        for (int i = 0; i < 64; i += 4) {
            float w0 = sW1[(128 + i    ) * 256 + k], w1 = sW1[(128 + i + 1) * 256 + k];
            float w2 = sW1[(128 + i + 2) * 256 + k], w3 = sW1[(128 + i + 3) * 256 + k];
            #pragma unroll
            for (int q = 0; q < 5; q++) {
                float4 xv = *(const float4*)&sX[idxJ[q] + i];
                acc[q] = fmaf(xv.x, w0, acc[q]);
                acc[q] = fmaf(xv.y, w1, acc[q]);
                acc[q] = fmaf(xv.z, w2, acc[q]);
                acc[q] = fmaf(xv.w, w3, acc[q]);
            }
        }
        #pragma unroll 2
        for (int i = 0; i < 64; i += 4) {
            float w0 = sW1[(192 + i    ) * 256 + k], w1 = sW1[(192 + i + 1) * 256 + k];
            float w2 = sW1[(192 + i + 2) * 256 + k], w3 = sW1[(192 + i + 3) * 256 + k];
            float4 g = *(const float4*)&sXg[i];
            #pragma unroll
            for (int q = 0; q < 5; q++) {
                acc[q] = fmaf(g.x, w0, acc[q]);
                acc[q] = fmaf(g.y, w1, acc[q]);
                acc[q] = fmaf(g.z, w2, acc[q]);
                acc[q] = fmaf(g.w, w3, acc[q]);
            }
        }
        #pragma unroll
        for (int q = 0; q < 5; q++)
            sS[(rg * 5 + q) * 256 + k] = fmaxf(acc[q], 0.0f);
    }
    __syncthreads();

    // smlp out (warps 8-15, 5 outputs each, lane-split dot) +
    // cmlp graph-term g[k] (threads 64..255)
    if (wid >= 8) {
        int w8 = wid - 8;
        #pragma unroll
        for (int q = 0; q < 5; q++) {
            int o = w8 * 5 + q;               // o in [0,40)
            int r = o >> 2, j = o & 3;
            float a = 0.f;
            #pragma unroll
            for (int kk = 0; kk < 256; kk += 32)
                a = fmaf(sS[r * 256 + kk + lane], sW2[(kk + lane) * 4 + j], a);
            #pragma unroll
            for (int off = 16; off > 0; off >>= 1)
                a += __shfl_xor_sync(0xffffffffu, a, off);
            if (lane == 0) sOutS[o] = sigm(a);
        }
    } else if (t >= 64 && t < 256) {
        int k = t - 64;
        float a = 0.f;
        #pragma unroll 4
        for (int i = 0; i < 64; i++)
            a = fmaf(sXg[i], cW1[(128 + i) * 192 + k], a);
        sG[k] = a;
    }
    __syncthreads();

    // cmlp hidden (63 x 192) -> sHid, 4 passes of 8 rows (float4 over i)
    if (t < 384) {
        int k = t % 192, half = t / 192;
        #pragma unroll 1
        for (int p = 0; p < 4; p++) {
            int r0 = p * 16 + half * 8;
            float acc[8];
            int bA[8], bB[8];
            #pragma unroll
            for (int q = 0; q < 8; q++) {
                int r = r0 + q;
                int rr = (r < ECNT) ? r : 0;
                acc[q] = 0.f;
                bA[q] = sAi[rr] * HID;
                bB[q] = sAj[rr] * HID;
            }
            #pragma unroll 2
            for (int i = 0; i < 64; i += 4) {
                float wa0 = cW1[(i    ) * 192 + k], wa1 = cW1[(i + 1) * 192 + k];
                float wa2 = cW1[(i + 2) * 192 + k], wa3 = cW1[(i + 3) * 192 + k];
                float wb0 = cW1[(64 + i    ) * 192 + k], wb1 = cW1[(64 + i + 1) * 192 + k];
                float wb2 = cW1[(64 + i + 2) * 192 + k], wb3 = cW1[(64 + i + 3) * 192 + k];
                #pragma unroll
                for (int q = 0; q < 8; q++) {
                    float4 xa = *(const float4*)&sX[bA[q] + i];
                    float4 xb = *(const float4*)&sX[bB[q] + i];
                    acc[q] = fmaf(xa.x, wa0, acc[q]);
                    acc[q] = fmaf(xa.y, wa1, acc[q]);
                    acc[q] = fmaf(xa.z, wa2, acc[q]);
                    acc[q] = fmaf(xa.w, wa3, acc[q]);
                    acc[q] = fmaf(xb.x, wb0, acc[q]);
                    acc[q] = fmaf(xb.y, wb1, acc[q]);
                    acc[q] = fmaf(xb.z, wb2, acc[q]);
                    acc[q] = fmaf(xb.w, wb3, acc[q]);
                }
            }
            #pragma unroll
            for (int q = 0; q < 8; q++) {
                int r = r0 + q;
                if (r < ECNT)
                    sHid[r * 192 + k] = fmaxf(acc[q] + sG[k], 0.0f);
            }
        }
    }
    __syncthreads();

    // cmlp out (63x3 = 189 outputs, one per warp-iteration, lane-split dot)
    for (int o = wid; o < ECNT * 3; o += NWARP) {
        int r = o / 3, j = o - r * 3;
        float a = 0.f;
        #pragma unroll
        for (int kk = 0; kk < 192; kk += 32)
            a = fmaf(sHid[r * 192 + kk + lane], cW2[(kk + lane) * 3 + j], a);
        #pragma unroll
        for (int off = 16; off > 0; off >>= 1)
            a += __shfl_xor_sync(0xffffffffu, a, off);
        if (lane == 0) sOutC[o] = sigm(a);
    }
    __syncthreads();

    // per-edge parent/child voltages; zero node accumulator (reuse sXg)
    if (t < MN) {
        float o1, o2;
        if (t < ECNT) { o1 = sOutC[t * 3 + 1]; o2 = sOutC[t * 3 + 2]; }
        else          { o1 = sOutS[(t - ECNT) * 4 + 2]; o2 = sOutS[(t - ECNT) * 4 + 3]; }
        sVp[t] = 0.9f + 0.2f * o1;
        sVc[t] = 0.9f + 0.2f * o2;
    }
    if (t < VN) sXg[t] = 0.f;
    __syncthreads();

    // scatter voltages to nodes via shared atomics (Incp/Incc are one-hot)
    if (t < MN) {
        int p = (t < ECNT) ? sAi[t] : sSi[t - ECNT];
        int c = (t < ECNT) ? sAj[t] : sSj[t - ECNT];
        atomicAdd(&sXg[p], sVp[t]);
        atomicAdd(&sXg[c], sVc[t]);
    }
    __syncthreads();

    // ---- output assembly: [p_flow(73) | v(64) | graph_topo(73)] -------------
    float* ob = out + b * OUTW;
    for (int i = t; i < OUTW; i += NT) {
        float val;
        if (i < ECNT) {
            val = sOutC[i * 3] - 0.5f;
        } else if (i < MN) {
            val = sOutS[(i - ECNT) * 4 + 1] - 0.5f;
        } else if (i < MN + VN) {
            int n = i - MN;
            val = (n == 0) ? 1.0f : Dinv[n * VN + n] * sXg[n];
        } else if (i < MN + VN + ECNT) {
            val = 1.0f;
        } else {
            val = sOutS[(i - (MN + VN + ECNT)) * 4];
        }
        ob[i] = val;
    }
}

extern "C" void kernel_launch(void* const* d_in, const int* in_sizes, int n_in,
                              void* d_out, int out_size) {
    const float* x       = (const float*)d_in[0];
    const float* A       = (const float*)d_in[1];
    const float* S       = (const float*)d_in[2];
    const float* embed_s = (const float*)d_in[3];
    const float* p0_Ws   = (const float*)d_in[4];
    const float* p0_Wi   = (const float*)d_in[5];
    const float* p0_Wj   = (const float*)d_in[6];
    const float* p0_U    = (const float*)d_in[7];
    const float* p0_V    = (const float*)d_in[8];
    const float* pl_Ws   = (const float*)d_in[9];
    const float* pl_Wi   = (const float*)d_in[10];
    const float* pl_Wj   = (const float*)d_in[11];
    const float* pl_U    = (const float*)d_in[12];
    const float* pl_V    = (const float*)d_in[13];
    const float* smlp_W1 = (const float*)d_in[14];
    const float* smlp_W2 = (const float*)d_in[15];
    const float* cmlp_W1 = (const float*)d_in[16];
    const float* cmlp_W2 = (const float*)d_in[17];
    const float* Dinv    = (const float*)d_in[18];
    const float* Incp    = (const float*)d_in[19];
    const float* Incc    = (const float*)d_in[20];
    const int*   edge_A  = (const int*)d_in[21];
    const int*   edge_S  = (const int*)d_in[22];
    float*       out     = (float*)d_out;

    cudaFuncSetAttribute(gnn_kernel, cudaFuncAttributeMaxDynamicSharedMemorySize,
                         SMEM_BYTES);

    preproc_kernel<<<1, 64>>>(A, S, edge_S);
    gnn_kernel<<<BN, NT, SMEM_BYTES>>>(x, embed_s,
                                       p0_Ws, p0_Wi, p0_Wj, p0_U, p0_V,
                                       pl_Ws, pl_Wi, pl_Wj, pl_U, pl_V,
                                       smlp_W1, smlp_W2, cmlp_W1, cmlp_W2,
                                       Dinv, Incp, Incc, edge_A, edge_S, out);
}